// round 1
// baseline (speedup 1.0000x reference)
#include <cuda_runtime.h>
#include <math.h>

#define FDIM 128
#define NMAX 50000
#define EMAX 800000
#define KPOST (13*FDIM)   /* 1664 */

// ---------------- scratch (static device globals; no allocation) -------------
__device__ __align__(16) int   g_deg[NMAX];
__device__ __align__(16) int   g_rowptr[NMAX+1];
__device__ __align__(16) int   g_cursor[NMAX];
__device__ __align__(16) int   g_srcs[EMAX];
__device__ __align__(16) float g_u[(size_t)NMAX*FDIM];
__device__ __align__(16) float g_v[(size_t)NMAX*FDIM];
__device__ __align__(16) float g_agg[(size_t)NMAX*4*FDIM];
__device__ __align__(16) float g_amp[NMAX];
__device__ __align__(16) float g_att[NMAX];
__device__ __align__(16) float g_Wt_pre[2*FDIM*FDIM];          // [256][128] (k-major)
__device__ __align__(16) float g_Wt_lin[FDIM*FDIM];            // [128][128] (k-major)
__device__ __align__(16) float g_Wt_comb[(size_t)KPOST*FDIM];  // [1664][128] = (W_lin@W_post)^T
__device__ __align__(16) float g_b_comb[FDIM];

// ---------------- CSR build --------------------------------------------------
__global__ void k_zero(int n){
    int i = blockIdx.x*blockDim.x + threadIdx.x;
    if (i < n) g_deg[i] = 0;
}

__global__ void k_hist(const int* __restrict__ dst, int E){
    int e = blockIdx.x*blockDim.x + threadIdx.x;
    if (e < E) atomicAdd(&g_deg[dst[e]], 1);
}

// single-block exclusive scan over N counts -> rowptr, cursor
__global__ void k_scan(int n){
    __shared__ int ss[1024];
    int t = threadIdx.x;
    int chunk = (n + 1023) >> 10;
    int lo = t*chunk;
    int hi = min(lo + chunk, n);
    int s = 0;
    for (int i = lo; i < hi; i++) s += g_deg[i];
    ss[t] = s;
    __syncthreads();
    for (int off = 1; off < 1024; off <<= 1){
        int v = (t >= off) ? ss[t-off] : 0;
        __syncthreads();
        ss[t] += v;
        __syncthreads();
    }
    int run = (t == 0) ? 0 : ss[t-1];
    for (int i = lo; i < hi; i++){
        g_rowptr[i] = run;
        g_cursor[i] = run;
        run += g_deg[i];
    }
    if (t == 1023) g_rowptr[n] = ss[1023];
}

__global__ void k_scatter(const int* __restrict__ src, const int* __restrict__ dst, int E){
    int e = blockIdx.x*blockDim.x + threadIdx.x;
    if (e < E){
        int d = dst[e];
        int p = atomicAdd(&g_cursor[d], 1);
        g_srcs[p] = src[e];
    }
}

// ---------------- weight prep ------------------------------------------------
// in: [FDIM][cols] row-major  ->  out: [cols][FDIM]
__global__ void k_transpose(const float* __restrict__ in, int cols, float* __restrict__ out){
    int total = FDIM*cols;
    for (int idx = blockIdx.x*blockDim.x + threadIdx.x; idx < total; idx += gridDim.x*blockDim.x){
        int f = idx / cols;
        int c = idx - f*cols;
        out[(size_t)c*FDIM + f] = in[idx];
    }
}

// Wt_comb[c][f] = sum_k W_lin[f][k] * W_post[k][c]   (uses pre-transposed W_lin)
__global__ void k_combine(const float* __restrict__ W_post){
    int c = blockIdx.x;
    int f = threadIdx.x;
    __shared__ float col[FDIM];
    col[f] = W_post[(size_t)f*KPOST + c];   // threadIdx as k
    __syncthreads();
    float s = 0.f;
    #pragma unroll 8
    for (int k = 0; k < FDIM; k++)
        s = fmaf(g_Wt_lin[k*FDIM + f], col[k], s);
    g_Wt_comb[(size_t)c*FDIM + f] = s;
}

// b_comb[f] = b_lin[f] + sum_k W_lin[f][k] * b_post[k]
__global__ void k_bias(const float* __restrict__ b_post, const float* __restrict__ b_lin){
    int f = threadIdx.x;
    float s = b_lin[f];
    #pragma unroll 8
    for (int k = 0; k < FDIM; k++)
        s = fmaf(g_Wt_lin[k*FDIM + f], b_post[k], s);
    g_b_comb[f] = s;
}

// ---------------- generic SGEMM:  C[M][128] = A[M][K] @ Wt[K][128] + bias ----
// BM=128, BN=128, BK=16, 256 threads, 8x8 microtile
__global__ void __launch_bounds__(256)
k_sgemm(const float* __restrict__ A, int M, int K,
        const float* __restrict__ Wt, const float* __restrict__ bias,
        float* __restrict__ C)
{
    __shared__ float As[16][128];
    __shared__ float Ws[16][128];
    int tid = threadIdx.x;
    int tx = tid & 15, ty = tid >> 4;
    int m0 = blockIdx.x * 128;

    float acc[8][8];
    #pragma unroll
    for (int i = 0; i < 8; i++)
        #pragma unroll
        for (int j = 0; j < 8; j++) acc[i][j] = 0.f;

    for (int k0 = 0; k0 < K; k0 += 16){
        #pragma unroll
        for (int i = 0; i < 2; i++){
            int idx = tid*2 + i;          // 0..511 float4 slots
            int r = idx >> 2, k4 = idx & 3;
            float4 v = make_float4(0.f,0.f,0.f,0.f);
            if (m0 + r < M)
                v = *(const float4*)(A + (size_t)(m0+r)*K + k0 + k4*4);
            As[k4*4+0][r] = v.x; As[k4*4+1][r] = v.y;
            As[k4*4+2][r] = v.z; As[k4*4+3][r] = v.w;
        }
        #pragma unroll
        for (int i = 0; i < 2; i++){
            int idx = tid*2 + i;
            *(float4*)(&Ws[0][0] + idx*4) = *(const float4*)(Wt + (size_t)k0*128 + idx*4);
        }
        __syncthreads();
        #pragma unroll
        for (int k = 0; k < 16; k++){
            float a[8], b[8];
            *(float4*)(a)   = *(const float4*)(&As[k][ty*8]);
            *(float4*)(a+4) = *(const float4*)(&As[k][ty*8+4]);
            *(float4*)(b)   = *(const float4*)(&Ws[k][tx*8]);
            *(float4*)(b+4) = *(const float4*)(&Ws[k][tx*8+4]);
            #pragma unroll
            for (int i = 0; i < 8; i++)
                #pragma unroll
                for (int j = 0; j < 8; j++)
                    acc[i][j] = fmaf(a[i], b[j], acc[i][j]);
        }
        __syncthreads();
    }

    float bb[8];
    #pragma unroll
    for (int j = 0; j < 8; j++) bb[j] = bias ? bias[tx*8+j] : 0.f;
    #pragma unroll
    for (int i = 0; i < 8; i++){
        int r = m0 + ty*8 + i;
        if (r < M){
            float o[8];
            #pragma unroll
            for (int j = 0; j < 8; j++) o[j] = acc[i][j] + bb[j];
            *(float4*)(C + (size_t)r*128 + tx*8)     = *(float4*)(o);
            *(float4*)(C + (size_t)r*128 + tx*8 + 4) = *(float4*)(o+4);
        }
    }
}

// ---------------- per-node aggregation over CSR ------------------------------
__global__ void k_agg(int n){
    int node = blockIdx.x;
    int f = threadIdx.x;
    int s0 = g_rowptr[node], s1 = g_rowptr[node+1];
    float uf = g_u[(size_t)node*FDIM + f];
    float mx = -3.402823466e38f, mn = 3.402823466e38f, sm = 0.f, sq = 0.f;
    for (int e = s0; e < s1; e++){
        int s = g_srcs[e];
        float val = uf + g_v[(size_t)s*FDIM + f];
        mx = fmaxf(mx, val);
        mn = fminf(mn, val);
        sm += val;
        sq = fmaf(val, val, sq);
    }
    int deg = s1 - s0;
    if (deg == 0){ mx = 0.f; mn = 0.f; }
    float dc   = fmaxf((float)deg, 1.f);
    float mean = sm / dc;
    float var  = sq / dc - mean*mean;
    float sd   = sqrtf(fmaxf(var, 0.f) + 1e-5f);
    size_t b = (size_t)node * (4*FDIM);
    g_agg[b + f]          = mx;
    g_agg[b + FDIM + f]   = mn;
    g_agg[b + 2*FDIM + f] = mean;
    g_agg[b + 3*FDIM + f] = sd;
    if (f == 0){
        float ld = logf(dc + 1.f);   // DELTA = 1.0
        g_amp[node] = ld;
        g_att[node] = 1.f / ld;
    }
}

// ---------------- fused post GEMM with virtual A, K=1664 ---------------------
// A[n][c] = x        for c in [0,128)
//         = agg      for c in [128,640)
//         = agg*amp  for c in [640,1152)
//         = agg*att  for c in [1152,1664)
__global__ void __launch_bounds__(256)
k_sgemm_post(const float* __restrict__ x, int M, float* __restrict__ C)
{
    __shared__ float As[16][128];
    __shared__ float Ws[16][128];
    int tid = threadIdx.x;
    int tx = tid & 15, ty = tid >> 4;
    int m0 = blockIdx.x * 128;

    float acc[8][8];
    #pragma unroll
    for (int i = 0; i < 8; i++)
        #pragma unroll
        for (int j = 0; j < 8; j++) acc[i][j] = 0.f;

    for (int k0 = 0; k0 < KPOST; k0 += 16){
        #pragma unroll
        for (int i = 0; i < 2; i++){
            int idx = tid*2 + i;
            int rl = idx >> 2, k4 = idx & 3;
            int r = m0 + rl;
            int c = k0 + k4*4;
            float4 v = make_float4(0.f,0.f,0.f,0.f);
            if (r < M){
                if (c < 128){
                    v = *(const float4*)(x + (size_t)r*128 + c);
                } else if (c < 640){
                    v = *(const float4*)(g_agg + (size_t)r*512 + (c - 128));
                } else if (c < 1152){
                    v = *(const float4*)(g_agg + (size_t)r*512 + (c - 640));
                    float s = g_amp[r];
                    v.x *= s; v.y *= s; v.z *= s; v.w *= s;
                } else {
                    v = *(const float4*)(g_agg + (size_t)r*512 + (c - 1152));
                    float s = g_att[r];
                    v.x *= s; v.y *= s; v.z *= s; v.w *= s;
                }
            }
            As[k4*4+0][rl] = v.x; As[k4*4+1][rl] = v.y;
            As[k4*4+2][rl] = v.z; As[k4*4+3][rl] = v.w;
        }
        #pragma unroll
        for (int i = 0; i < 2; i++){
            int idx = tid*2 + i;
            *(float4*)(&Ws[0][0] + idx*4) = *(const float4*)(g_Wt_comb + (size_t)k0*128 + idx*4);
        }
        __syncthreads();
        #pragma unroll
        for (int k = 0; k < 16; k++){
            float a[8], b[8];
            *(float4*)(a)   = *(const float4*)(&As[k][ty*8]);
            *(float4*)(a+4) = *(const float4*)(&As[k][ty*8+4]);
            *(float4*)(b)   = *(const float4*)(&Ws[k][tx*8]);
            *(float4*)(b+4) = *(const float4*)(&Ws[k][tx*8+4]);
            #pragma unroll
            for (int i = 0; i < 8; i++)
                #pragma unroll
                for (int j = 0; j < 8; j++)
                    acc[i][j] = fmaf(a[i], b[j], acc[i][j]);
        }
        __syncthreads();
    }

    #pragma unroll
    for (int i = 0; i < 8; i++){
        int r = m0 + ty*8 + i;
        if (r < M){
            float o[8];
            #pragma unroll
            for (int j = 0; j < 8; j++) o[j] = acc[i][j] + g_b_comb[tx*8+j];
            *(float4*)(C + (size_t)r*128 + tx*8)     = *(float4*)(o);
            *(float4*)(C + (size_t)r*128 + tx*8 + 4) = *(float4*)(o+4);
        }
    }
}

// ---------------- launch -----------------------------------------------------
extern "C" void kernel_launch(void* const* d_in, const int* in_sizes, int n_in,
                              void* d_out, int out_size)
{
    const float* x      = (const float*)d_in[0];
    const int*   ei     = (const int*)  d_in[1];
    const float* W_pre  = (const float*)d_in[2];
    const float* b_pre  = (const float*)d_in[3];
    const float* W_post = (const float*)d_in[4];
    const float* b_post = (const float*)d_in[5];
    const float* W_lin  = (const float*)d_in[6];
    const float* b_lin  = (const float*)d_in[7];
    float* out = (float*)d_out;

    int N = in_sizes[0] / FDIM;
    int E = in_sizes[1] / 2;
    const int* src = ei;        // edge_index[0] = x_j (source)
    const int* dst = ei + E;    // edge_index[1] = x_i (destination)

    void *p_u = 0, *p_v = 0, *p_wtpre = 0, *p_wtlin = 0;
    cudaGetSymbolAddress(&p_u, g_u);
    cudaGetSymbolAddress(&p_v, g_v);
    cudaGetSymbolAddress(&p_wtpre, g_Wt_pre);
    cudaGetSymbolAddress(&p_wtlin, g_Wt_lin);

    // CSR build
    k_zero   <<<(N+255)/256, 256>>>(N);
    k_hist   <<<(E+255)/256, 256>>>(dst, E);
    k_scan   <<<1, 1024>>>(N);
    k_scatter<<<(E+255)/256, 256>>>(src, dst, E);

    // weight prep
    k_transpose<<<128, 256>>>(W_pre, 2*FDIM, (float*)p_wtpre);
    k_transpose<<<64, 256>>>(W_lin, FDIM, (float*)p_wtlin);
    k_combine<<<KPOST, FDIM>>>(W_post);
    k_bias<<<1, FDIM>>>(b_post, b_lin);

    // u = x@Wi^T + b_pre ; v = x@Wj^T   (W_pre split: cols [0,128) dst, [128,256) src)
    int gm = (N + 127) / 128;
    k_sgemm<<<gm, 256>>>(x, N, FDIM, (const float*)p_wtpre, b_pre, (float*)p_u);
    k_sgemm<<<gm, 256>>>(x, N, FDIM, (const float*)p_wtpre + FDIM*FDIM, nullptr, (float*)p_v);

    // segment aggregation (max/min/mean/std) + scalers
    k_agg<<<N, FDIM>>>(N);

    // fused: out = [x | agg | agg*amp | agg*att] @ (W_lin@W_post)^T + b_comb
    k_sgemm_post<<<gm, 256>>>(x, N, out);
}

// round 2
// speedup vs baseline: 1.6950x; 1.6950x over previous
#include <cuda_runtime.h>
#include <math.h>
#include <stdint.h>

#define FDIM 128
#define NMAX 50000
#define EMAX 800000
#define KPOST (13*FDIM)   /* 1664 */

// ---------------- scratch (static device globals; no allocation) -------------
__device__ __align__(16) int   g_deg[NMAX];
__device__ __align__(16) int   g_rowptr[NMAX+1];
__device__ __align__(16) int   g_cursor[NMAX];
__device__ __align__(16) int   g_srcs[EMAX];
__device__ __align__(16) float g_u[(size_t)NMAX*FDIM];
__device__ __align__(16) float g_v[(size_t)NMAX*FDIM];
__device__ __align__(16) float g_agg[(size_t)NMAX*4*FDIM];
__device__ __align__(16) float g_amp[NMAX];
__device__ __align__(16) float g_att[NMAX];
__device__ __align__(16) float g_Wt_pre[2*FDIM*FDIM];          // [256][128] (k-major)
__device__ __align__(16) float g_Wt_lin[FDIM*FDIM];            // [128][128] (k-major)
__device__ __align__(16) float g_Wt_comb[(size_t)KPOST*FDIM];  // [1664][128], tf32-rounded
__device__ __align__(16) float g_b_comb[FDIM];

__device__ __forceinline__ uint32_t f2tf32(float f){
    uint32_t r;
    asm("cvt.rna.tf32.f32 %0, %1;" : "=r"(r) : "f"(f));
    return r;
}

// ---------------- CSR build --------------------------------------------------
__global__ void k_zero(int n){
    int i = blockIdx.x*blockDim.x + threadIdx.x;
    if (i < n) g_deg[i] = 0;
}

__global__ void k_hist(const int* __restrict__ dst, int E){
    int e = blockIdx.x*blockDim.x + threadIdx.x;
    if (e < E) atomicAdd(&g_deg[dst[e]], 1);
}

__global__ void k_scan(int n){
    __shared__ int ss[1024];
    int t = threadIdx.x;
    int chunk = (n + 1023) >> 10;
    int lo = t*chunk;
    int hi = min(lo + chunk, n);
    int s = 0;
    for (int i = lo; i < hi; i++) s += g_deg[i];
    ss[t] = s;
    __syncthreads();
    for (int off = 1; off < 1024; off <<= 1){
        int v = (t >= off) ? ss[t-off] : 0;
        __syncthreads();
        ss[t] += v;
        __syncthreads();
    }
    int run = (t == 0) ? 0 : ss[t-1];
    for (int i = lo; i < hi; i++){
        g_rowptr[i] = run;
        g_cursor[i] = run;
        run += g_deg[i];
    }
    if (t == 1023) g_rowptr[n] = ss[1023];
}

__global__ void k_scatter(const int* __restrict__ src, const int* __restrict__ dst, int E){
    int e = blockIdx.x*blockDim.x + threadIdx.x;
    if (e < E){
        int d = dst[e];
        int p = atomicAdd(&g_cursor[d], 1);
        g_srcs[p] = src[e];
    }
}

// ---------------- weight prep ------------------------------------------------
__global__ void k_transpose(const float* __restrict__ in, int cols, float* __restrict__ out){
    int total = FDIM*cols;
    for (int idx = blockIdx.x*blockDim.x + threadIdx.x; idx < total; idx += gridDim.x*blockDim.x){
        int f = idx / cols;
        int c = idx - f*cols;
        out[(size_t)c*FDIM + f] = in[idx];
    }
}

// Wt_comb[c][f] = sum_k W_lin[f][k] * W_post[k][c], rounded to tf32
__global__ void k_combine(const float* __restrict__ W_post){
    int c = blockIdx.x;
    int f = threadIdx.x;
    __shared__ float col[FDIM];
    col[f] = W_post[(size_t)f*KPOST + c];
    __syncthreads();
    float s = 0.f;
    #pragma unroll 8
    for (int k = 0; k < FDIM; k++)
        s = fmaf(g_Wt_lin[k*FDIM + f], col[k], s);
    g_Wt_comb[(size_t)c*FDIM + f] = __uint_as_float(f2tf32(s));
}

__global__ void k_bias(const float* __restrict__ b_post, const float* __restrict__ b_lin){
    int f = threadIdx.x;
    float s = b_lin[f];
    #pragma unroll 8
    for (int k = 0; k < FDIM; k++)
        s = fmaf(g_Wt_lin[k*FDIM + f], b_post[k], s);
    g_b_comb[f] = s;
}

// ---------------- fp32 SGEMM for u/v (kept exact) ----------------------------
__global__ void __launch_bounds__(256)
k_sgemm(const float* __restrict__ A, int M, int K,
        const float* __restrict__ Wt, const float* __restrict__ bias,
        float* __restrict__ C)
{
    __shared__ float As[16][128];
    __shared__ float Ws[16][128];
    int tid = threadIdx.x;
    int tx = tid & 15, ty = tid >> 4;
    int m0 = blockIdx.x * 128;

    float acc[8][8];
    #pragma unroll
    for (int i = 0; i < 8; i++)
        #pragma unroll
        for (int j = 0; j < 8; j++) acc[i][j] = 0.f;

    for (int k0 = 0; k0 < K; k0 += 16){
        #pragma unroll
        for (int i = 0; i < 2; i++){
            int idx = tid*2 + i;
            int r = idx >> 2, k4 = idx & 3;
            float4 v = make_float4(0.f,0.f,0.f,0.f);
            if (m0 + r < M)
                v = *(const float4*)(A + (size_t)(m0+r)*K + k0 + k4*4);
            As[k4*4+0][r] = v.x; As[k4*4+1][r] = v.y;
            As[k4*4+2][r] = v.z; As[k4*4+3][r] = v.w;
        }
        #pragma unroll
        for (int i = 0; i < 2; i++){
            int idx = tid*2 + i;
            *(float4*)(&Ws[0][0] + idx*4) = *(const float4*)(Wt + (size_t)k0*128 + idx*4);
        }
        __syncthreads();
        #pragma unroll
        for (int k = 0; k < 16; k++){
            float a[8], b[8];
            *(float4*)(a)   = *(const float4*)(&As[k][ty*8]);
            *(float4*)(a+4) = *(const float4*)(&As[k][ty*8+4]);
            *(float4*)(b)   = *(const float4*)(&Ws[k][tx*8]);
            *(float4*)(b+4) = *(const float4*)(&Ws[k][tx*8+4]);
            #pragma unroll
            for (int i = 0; i < 8; i++)
                #pragma unroll
                for (int j = 0; j < 8; j++)
                    acc[i][j] = fmaf(a[i], b[j], acc[i][j]);
        }
        __syncthreads();
    }

    float bb[8];
    #pragma unroll
    for (int j = 0; j < 8; j++) bb[j] = bias ? bias[tx*8+j] : 0.f;
    #pragma unroll
    for (int i = 0; i < 8; i++){
        int r = m0 + ty*8 + i;
        if (r < M){
            float o[8];
            #pragma unroll
            for (int j = 0; j < 8; j++) o[j] = acc[i][j] + bb[j];
            *(float4*)(C + (size_t)r*128 + tx*8)     = *(float4*)(o);
            *(float4*)(C + (size_t)r*128 + tx*8 + 4) = *(float4*)(o+4);
        }
    }
}

// ---------------- per-node aggregation over CSR ------------------------------
__global__ void k_agg(int n){
    int node = blockIdx.x;
    int f = threadIdx.x;
    int s0 = g_rowptr[node], s1 = g_rowptr[node+1];
    float uf = g_u[(size_t)node*FDIM + f];
    float mx = -3.402823466e38f, mn = 3.402823466e38f, sm = 0.f, sq = 0.f;
    for (int e = s0; e < s1; e++){
        int s = g_srcs[e];
        float val = uf + g_v[(size_t)s*FDIM + f];
        mx = fmaxf(mx, val);
        mn = fminf(mn, val);
        sm += val;
        sq = fmaf(val, val, sq);
    }
    int deg = s1 - s0;
    if (deg == 0){ mx = 0.f; mn = 0.f; }
    float dc   = fmaxf((float)deg, 1.f);
    float mean = sm / dc;
    float var  = sq / dc - mean*mean;
    float sd   = sqrtf(fmaxf(var, 0.f) + 1e-5f);
    size_t b = (size_t)node * (4*FDIM);
    g_agg[b + f]          = mx;
    g_agg[b + FDIM + f]   = mn;
    g_agg[b + 2*FDIM + f] = mean;
    g_agg[b + 3*FDIM + f] = sd;
    if (f == 0){
        float ld = logf(dc + 1.f);   // DELTA = 1.0
        g_amp[node] = ld;
        g_att[node] = 1.f / ld;
    }
}

// ---------------- TF32 tensor-core post GEMM, K=1664 -------------------------
// C[M][128] = [x | agg | agg*amp | agg*att] @ Wt_comb + b_comb
// BM=128 BN=128 BK=32; 8 warps as 4(m)x2(n); warp = 32x64 via 2x8 m16n8k8.
__global__ void __launch_bounds__(256)
k_post_tf32(const float* __restrict__ x, int M, float* __restrict__ C)
{
    __shared__ uint32_t As[32][132];   // [k][m], pad 132 -> conflict-free frag loads
    __shared__ uint32_t Ws[32][132];   // [k][n]
    int tid  = threadIdx.x;
    int m0   = blockIdx.x * 128;
    int wid  = tid >> 5, lane = tid & 31;
    int wm   = (wid >> 1) * 32;
    int wn   = (wid & 1) * 64;
    int grp  = lane >> 2, qid = lane & 3;

    float acc[2][8][4];
    #pragma unroll
    for (int mt = 0; mt < 2; mt++)
        #pragma unroll
        for (int nt = 0; nt < 8; nt++)
            #pragma unroll
            for (int q = 0; q < 4; q++) acc[mt][nt][q] = 0.f;

    for (int k0 = 0; k0 < KPOST; k0 += 32){
        // --- load virtual-A tile (128 rows x 32 k), tf32-round into smem ---
        #pragma unroll
        for (int i = 0; i < 4; i++){
            int idx = tid + 256*i;          // 0..1023 float4 slots
            int rl  = idx >> 3;             // row 0..127
            int k4  = idx & 7;              // float4 within 32-k row
            int r   = m0 + rl;
            int c   = k0 + k4*4;
            float4 v = make_float4(0.f,0.f,0.f,0.f);
            if (r < M){
                if (c < 128){
                    v = *(const float4*)(x + (size_t)r*128 + c);
                } else if (c < 640){
                    v = *(const float4*)(g_agg + (size_t)r*512 + (c - 128));
                } else if (c < 1152){
                    v = *(const float4*)(g_agg + (size_t)r*512 + (c - 640));
                    float s = g_amp[r];
                    v.x *= s; v.y *= s; v.z *= s; v.w *= s;
                } else {
                    v = *(const float4*)(g_agg + (size_t)r*512 + (c - 1152));
                    float s = g_att[r];
                    v.x *= s; v.y *= s; v.z *= s; v.w *= s;
                }
            }
            As[k4*4+0][rl] = f2tf32(v.x);
            As[k4*4+1][rl] = f2tf32(v.y);
            As[k4*4+2][rl] = f2tf32(v.z);
            As[k4*4+3][rl] = f2tf32(v.w);
        }
        // --- load W tile (32 k x 128 n), already tf32-rounded ---
        #pragma unroll
        for (int i = 0; i < 4; i++){
            int idx = tid + 256*i;          // 0..1023
            int k   = idx >> 5;             // 0..31
            int n4  = idx & 31;
            float4 w = *(const float4*)(g_Wt_comb + (size_t)(k0+k)*128 + n4*4);
            Ws[k][n4*4+0] = __float_as_uint(w.x);
            Ws[k][n4*4+1] = __float_as_uint(w.y);
            Ws[k][n4*4+2] = __float_as_uint(w.z);
            Ws[k][n4*4+3] = __float_as_uint(w.w);
        }
        __syncthreads();

        #pragma unroll
        for (int ks = 0; ks < 4; ks++){
            int kk = ks*8;
            uint32_t a[2][4], b[8][2];
            #pragma unroll
            for (int mt = 0; mt < 2; mt++){
                int row = wm + mt*16 + grp;
                a[mt][0] = As[kk+qid  ][row];
                a[mt][1] = As[kk+qid  ][row+8];
                a[mt][2] = As[kk+qid+4][row];
                a[mt][3] = As[kk+qid+4][row+8];
            }
            #pragma unroll
            for (int nt = 0; nt < 8; nt++){
                int col = wn + nt*8 + grp;
                b[nt][0] = Ws[kk+qid  ][col];
                b[nt][1] = Ws[kk+qid+4][col];
            }
            #pragma unroll
            for (int mt = 0; mt < 2; mt++)
                #pragma unroll
                for (int nt = 0; nt < 8; nt++){
                    asm volatile(
                        "mma.sync.aligned.m16n8k8.row.col.f32.tf32.tf32.f32 "
                        "{%0,%1,%2,%3}, {%4,%5,%6,%7}, {%8,%9}, {%0,%1,%2,%3};\n"
                        : "+f"(acc[mt][nt][0]), "+f"(acc[mt][nt][1]),
                          "+f"(acc[mt][nt][2]), "+f"(acc[mt][nt][3])
                        : "r"(a[mt][0]), "r"(a[mt][1]), "r"(a[mt][2]), "r"(a[mt][3]),
                          "r"(b[nt][0]), "r"(b[nt][1]));
                }
        }
        __syncthreads();
    }

    // --- epilogue: add bias, store ---
    #pragma unroll
    for (int mt = 0; mt < 2; mt++){
        int row0 = m0 + wm + mt*16 + grp;
        #pragma unroll
        for (int nt = 0; nt < 8; nt++){
            int col = wn + nt*8 + 2*qid;
            float b0 = g_b_comb[col], b1 = g_b_comb[col+1];
            if (row0 < M){
                float2 v = make_float2(acc[mt][nt][0] + b0, acc[mt][nt][1] + b1);
                *(float2*)(C + (size_t)row0*128 + col) = v;
            }
            if (row0 + 8 < M){
                float2 v = make_float2(acc[mt][nt][2] + b0, acc[mt][nt][3] + b1);
                *(float2*)(C + (size_t)(row0+8)*128 + col) = v;
            }
        }
    }
}

// ---------------- launch -----------------------------------------------------
extern "C" void kernel_launch(void* const* d_in, const int* in_sizes, int n_in,
                              void* d_out, int out_size)
{
    const float* x      = (const float*)d_in[0];
    const int*   ei     = (const int*)  d_in[1];
    const float* W_pre  = (const float*)d_in[2];
    const float* b_pre  = (const float*)d_in[3];
    const float* W_post = (const float*)d_in[4];
    const float* b_post = (const float*)d_in[5];
    const float* W_lin  = (const float*)d_in[6];
    const float* b_lin  = (const float*)d_in[7];
    float* out = (float*)d_out;

    int N = in_sizes[0] / FDIM;
    int E = in_sizes[1] / 2;
    const int* src = ei;        // edge_index[0] = x_j (source)
    const int* dst = ei + E;    // edge_index[1] = x_i (destination)

    void *p_u = 0, *p_v = 0, *p_wtpre = 0, *p_wtlin = 0;
    cudaGetSymbolAddress(&p_u, g_u);
    cudaGetSymbolAddress(&p_v, g_v);
    cudaGetSymbolAddress(&p_wtpre, g_Wt_pre);
    cudaGetSymbolAddress(&p_wtlin, g_Wt_lin);

    // CSR build
    k_zero   <<<(N+255)/256, 256>>>(N);
    k_hist   <<<(E+255)/256, 256>>>(dst, E);
    k_scan   <<<1, 1024>>>(N);
    k_scatter<<<(E+255)/256, 256>>>(src, dst, E);

    // weight prep
    k_transpose<<<128, 256>>>(W_pre, 2*FDIM, (float*)p_wtpre);
    k_transpose<<<64, 256>>>(W_lin, FDIM, (float*)p_wtlin);
    k_combine<<<KPOST, FDIM>>>(W_post);
    k_bias<<<1, FDIM>>>(b_post, b_lin);

    // u = x@Wi^T + b_pre ; v = x@Wj^T   (exact fp32)
    int gm = (N + 127) / 128;
    k_sgemm<<<gm, 256>>>(x, N, FDIM, (const float*)p_wtpre, b_pre, (float*)p_u);
    k_sgemm<<<gm, 256>>>(x, N, FDIM, (const float*)p_wtpre + FDIM*FDIM, nullptr, (float*)p_v);

    // segment aggregation (max/min/mean/std) + scalers
    k_agg<<<N, FDIM>>>(N);

    // fused tf32 tensor-core post GEMM
    k_post_tf32<<<gm, 256>>>(x, N, out);
}

// round 4
// speedup vs baseline: 2.0185x; 1.1908x over previous
#include <cuda_runtime.h>
#include <math.h>
#include <stdint.h>

#define FDIM 128
#define NMAX 50000
#define EMAX 800000
#define KPOST (13*FDIM)   /* 1664 */

// ---------------- scratch (static device globals; no allocation) -------------
__device__ __align__(16) int   g_deg[NMAX];
__device__ __align__(16) int   g_rowptr[NMAX+1];
__device__ __align__(16) int   g_cursor[NMAX];
__device__ __align__(16) int   g_srcs[EMAX];
__device__ __align__(16) float g_u[(size_t)NMAX*FDIM];
__device__ __align__(16) float g_v[(size_t)NMAX*FDIM];
__device__ __align__(16) float g_agg[(size_t)NMAX*4*FDIM];
__device__ __align__(16) float g_amp[NMAX];
__device__ __align__(16) float g_att[NMAX];
__device__ __align__(16) float g_Wt_uv[128*256];               // [k][256], tf32-rounded
__device__ __align__(16) float g_Wt_lin[FDIM*FDIM];            // [128][128] (k-major)
__device__ __align__(16) float g_Wt_comb[(size_t)KPOST*FDIM];  // [1664][128], tf32-rounded
__device__ __align__(16) float g_b_comb[FDIM];

__device__ __forceinline__ uint32_t f2tf32(float f){
    uint32_t r;
    asm("cvt.rna.tf32.f32 %0, %1;" : "=r"(r) : "f"(f));
    return r;
}
__device__ __forceinline__ void cp_async16(uint32_t smem, const void* gmem){
    asm volatile("cp.async.cg.shared.global [%0], [%1], 16;\n" :: "r"(smem), "l"(gmem));
}
#define CP_COMMIT() asm volatile("cp.async.commit_group;\n" ::: "memory")
#define CP_WAIT0()  asm volatile("cp.async.wait_group 0;\n" ::: "memory")

// ---------------- CSR build --------------------------------------------------
__global__ void k_zero(int n){
    int i = blockIdx.x*blockDim.x + threadIdx.x;
    if (i < n) g_deg[i] = 0;
}

__global__ void k_hist(const int* __restrict__ dst, int E){
    int e = blockIdx.x*blockDim.x + threadIdx.x;
    if (e < E) atomicAdd(&g_deg[dst[e]], 1);
}

__global__ void k_scan(int n){
    __shared__ int ss[1024];
    int t = threadIdx.x;
    int chunk = (n + 1023) >> 10;
    int lo = t*chunk;
    int hi = min(lo + chunk, n);
    int s = 0;
    for (int i = lo; i < hi; i++) s += g_deg[i];
    ss[t] = s;
    __syncthreads();
    for (int off = 1; off < 1024; off <<= 1){
        int v = (t >= off) ? ss[t-off] : 0;
        __syncthreads();
        ss[t] += v;
        __syncthreads();
    }
    int run = (t == 0) ? 0 : ss[t-1];
    for (int i = lo; i < hi; i++){
        g_rowptr[i] = run;
        g_cursor[i] = run;
        run += g_deg[i];
    }
    if (t == 1023) g_rowptr[n] = ss[1023];
}

__global__ void k_scatter(const int* __restrict__ src, const int* __restrict__ dst, int E){
    int e = blockIdx.x*blockDim.x + threadIdx.x;
    if (e < E){
        int d = dst[e];
        int p = atomicAdd(&g_cursor[d], 1);
        g_srcs[p] = src[e];
    }
}

// ---------------- weight prep ------------------------------------------------
// W_pre [128][256] row-major -> Wuv[k][j]: j<128: W_pre[j][k] (u), else W_pre[j-128][128+k] (v)
__global__ void k_prep_uv(const float* __restrict__ W_pre){
    int idx = blockIdx.x*256 + threadIdx.x;
    if (idx < 128*256){
        int k = idx >> 8, j = idx & 255;
        float val = W_pre[(size_t)(j & 127)*256 + ((j >> 7) ? (128 + k) : k)];
        g_Wt_uv[idx] = __uint_as_float(f2tf32(val));
    }
}

// W_lin [128][128] -> k-major transpose
__global__ void k_transpose_lin(const float* __restrict__ in){
    int idx = blockIdx.x*256 + threadIdx.x;
    if (idx < FDIM*FDIM){
        int f = idx >> 7, c = idx & 127;
        g_Wt_lin[c*FDIM + f] = in[idx];
    }
}

// Wt_comb[c][f] = sum_k W_lin[f][k] * W_post[k][c], rounded to tf32
__global__ void k_combine(const float* __restrict__ W_post){
    int c = blockIdx.x;
    int f = threadIdx.x;
    __shared__ float col[FDIM];
    col[f] = W_post[(size_t)f*KPOST + c];
    __syncthreads();
    float s = 0.f;
    #pragma unroll 8
    for (int k = 0; k < FDIM; k++)
        s = fmaf(g_Wt_lin[k*FDIM + f], col[k], s);
    g_Wt_comb[(size_t)c*FDIM + f] = __uint_as_float(f2tf32(s));
}

__global__ void k_bias(const float* __restrict__ b_post, const float* __restrict__ b_lin){
    int f = threadIdx.x;
    float s = b_lin[f];
    #pragma unroll 8
    for (int k = 0; k < FDIM; k++)
        s = fmaf(g_Wt_lin[k*FDIM + f], b_post[k], s);
    g_b_comb[f] = s;
}

// ---------------- fused u/v TF32 GEMM: [u|v] = x @ Wuv  (K=128) --------------
// gridDim.y: 0 -> u (bias b_pre), 1 -> v (no bias)
__global__ void __launch_bounds__(256)
k_uv_tf32(const float* __restrict__ x, int M, const float* __restrict__ b_pre)
{
    __shared__ uint32_t As[32][132];
    __shared__ uint32_t Ws[32][132];
    int tid  = threadIdx.x;
    int m0   = blockIdx.x * 128;
    int half = blockIdx.y;
    float* Cout = half ? g_v : g_u;
    int wid  = tid >> 5, lane = tid & 31;
    int wm   = (wid >> 1) * 32;
    int wn   = (wid & 1) * 64;
    int grp  = lane >> 2, qid = lane & 3;

    float acc[2][8][4];
    #pragma unroll
    for (int mt = 0; mt < 2; mt++)
        #pragma unroll
        for (int nt = 0; nt < 8; nt++)
            #pragma unroll
            for (int q = 0; q < 4; q++) acc[mt][nt][q] = 0.f;

    for (int k0 = 0; k0 < 128; k0 += 32){
        #pragma unroll
        for (int i = 0; i < 4; i++){
            int idx = tid + 256*i;
            int rl  = idx >> 3, k4 = idx & 7;
            int r   = m0 + rl;
            float4 v = make_float4(0.f,0.f,0.f,0.f);
            if (r < M) v = *(const float4*)(x + (size_t)r*128 + k0 + k4*4);
            As[k4*4+0][rl] = f2tf32(v.x);
            As[k4*4+1][rl] = f2tf32(v.y);
            As[k4*4+2][rl] = f2tf32(v.z);
            As[k4*4+3][rl] = f2tf32(v.w);
        }
        #pragma unroll
        for (int i = 0; i < 4; i++){
            int idx = tid + 256*i;
            int k   = idx >> 5, n4 = idx & 31;
            float4 w = *(const float4*)(g_Wt_uv + (size_t)(k0+k)*256 + half*128 + n4*4);
            Ws[k][n4*4+0] = __float_as_uint(w.x);
            Ws[k][n4*4+1] = __float_as_uint(w.y);
            Ws[k][n4*4+2] = __float_as_uint(w.z);
            Ws[k][n4*4+3] = __float_as_uint(w.w);
        }
        __syncthreads();
        #pragma unroll
        for (int ks = 0; ks < 4; ks++){
            int kk = ks*8;
            uint32_t a[2][4], b[8][2];
            #pragma unroll
            for (int mt = 0; mt < 2; mt++){
                int row = wm + mt*16 + grp;
                a[mt][0] = As[kk+qid  ][row];
                a[mt][1] = As[kk+qid  ][row+8];
                a[mt][2] = As[kk+qid+4][row];
                a[mt][3] = As[kk+qid+4][row+8];
            }
            #pragma unroll
            for (int nt = 0; nt < 8; nt++){
                int col = wn + nt*8 + grp;
                b[nt][0] = Ws[kk+qid  ][col];
                b[nt][1] = Ws[kk+qid+4][col];
            }
            #pragma unroll
            for (int mt = 0; mt < 2; mt++)
                #pragma unroll
                for (int nt = 0; nt < 8; nt++){
                    asm volatile(
                        "mma.sync.aligned.m16n8k8.row.col.f32.tf32.tf32.f32 "
                        "{%0,%1,%2,%3}, {%4,%5,%6,%7}, {%8,%9}, {%0,%1,%2,%3};\n"
                        : "+f"(acc[mt][nt][0]), "+f"(acc[mt][nt][1]),
                          "+f"(acc[mt][nt][2]), "+f"(acc[mt][nt][3])
                        : "r"(a[mt][0]), "r"(a[mt][1]), "r"(a[mt][2]), "r"(a[mt][3]),
                          "r"(b[nt][0]), "r"(b[nt][1]));
                }
        }
        __syncthreads();
    }

    #pragma unroll
    for (int mt = 0; mt < 2; mt++){
        int row0 = m0 + wm + mt*16 + grp;
        #pragma unroll
        for (int nt = 0; nt < 8; nt++){
            int col = wn + nt*8 + 2*qid;
            float b0 = half ? 0.f : b_pre[col];
            float b1 = half ? 0.f : b_pre[col+1];
            if (row0 < M){
                float2 v = make_float2(acc[mt][nt][0] + b0, acc[mt][nt][1] + b1);
                *(float2*)(Cout + (size_t)row0*128 + col) = v;
            }
            if (row0 + 8 < M){
                float2 v = make_float2(acc[mt][nt][2] + b0, acc[mt][nt][3] + b1);
                *(float2*)(Cout + (size_t)(row0+8)*128 + col) = v;
            }
        }
    }
}

// ---------------- per-node aggregation over CSR (4-way MLP) ------------------
__global__ void k_agg(int n){
    int node = blockIdx.x;
    int f = threadIdx.x;
    int s0 = g_rowptr[node], s1 = g_rowptr[node+1];
    float uf = g_u[(size_t)node*FDIM + f];
    float mx = -3.402823466e38f, mn = 3.402823466e38f, sm = 0.f, sq = 0.f;
    int e = s0;
    for (; e + 3 < s1; e += 4){
        int i0 = g_srcs[e], i1 = g_srcs[e+1], i2 = g_srcs[e+2], i3 = g_srcs[e+3];
        float v0 = g_v[(size_t)i0*FDIM + f];
        float v1 = g_v[(size_t)i1*FDIM + f];
        float v2 = g_v[(size_t)i2*FDIM + f];
        float v3 = g_v[(size_t)i3*FDIM + f];
        float a0 = uf + v0, a1 = uf + v1, a2 = uf + v2, a3 = uf + v3;
        mx = fmaxf(mx, fmaxf(fmaxf(a0, a1), fmaxf(a2, a3)));
        mn = fminf(mn, fminf(fminf(a0, a1), fminf(a2, a3)));
        sm += a0 + a1 + a2 + a3;
        sq = fmaf(a0, a0, sq); sq = fmaf(a1, a1, sq);
        sq = fmaf(a2, a2, sq); sq = fmaf(a3, a3, sq);
    }
    for (; e < s1; e++){
        int s = g_srcs[e];
        float val = uf + g_v[(size_t)s*FDIM + f];
        mx = fmaxf(mx, val);
        mn = fminf(mn, val);
        sm += val;
        sq = fmaf(val, val, sq);
    }
    int deg = s1 - s0;
    if (deg == 0){ mx = 0.f; mn = 0.f; }
    float dc   = fmaxf((float)deg, 1.f);
    float mean = sm / dc;
    float var  = sq / dc - mean*mean;
    float sd   = sqrtf(fmaxf(var, 0.f) + 1e-5f);
    size_t b = (size_t)node * (4*FDIM);
    g_agg[b + f]          = mx;
    g_agg[b + FDIM + f]   = mn;
    g_agg[b + 2*FDIM + f] = mean;
    g_agg[b + 3*FDIM + f] = sd;
    if (f == 0){
        float ld = logf(dc + 1.f);   // DELTA = 1.0
        g_amp[node] = ld;
        g_att[node] = 1.f / ld;
    }
}

// ---------------- TF32 post GEMM, K=1664, double-buffered + cp.async ---------
// dynamic smem: As[2][32][132] then Ws[2][32][132]  (uint32), total 67584 B
#define TILE_U32 (32*132)
#define POST_SMEM_BYTES (4*TILE_U32*4)

__global__ void __launch_bounds__(256)
k_post_tf32(const float* __restrict__ x, int M, float* __restrict__ C)
{
    extern __shared__ uint32_t sm[];
    uint32_t* Asb[2] = { sm,              sm + TILE_U32 };
    uint32_t* Wsb[2] = { sm + 2*TILE_U32, sm + 3*TILE_U32 };

    int tid  = threadIdx.x;
    int m0   = blockIdx.x * 128;
    int wid  = tid >> 5, lane = tid & 31;
    int wm   = (wid >> 1) * 32;
    int wn   = (wid & 1) * 64;
    int grp  = lane >> 2, qid = lane & 3;

    float acc[2][8][4];
    #pragma unroll
    for (int mt = 0; mt < 2; mt++)
        #pragma unroll
        for (int nt = 0; nt < 8; nt++)
            #pragma unroll
            for (int q = 0; q < 4; q++) acc[mt][nt][q] = 0.f;

    float4 ra[4];

    auto loadA = [&](int k0){
        #pragma unroll
        for (int i = 0; i < 4; i++){
            int idx = tid + 256*i;
            int rl  = idx >> 3, k4 = idx & 7;
            int r   = m0 + rl;
            int c   = k0 + k4*4;
            float4 v = make_float4(0.f,0.f,0.f,0.f);
            if (r < M){
                if (c < 128){
                    v = *(const float4*)(x + (size_t)r*128 + c);
                } else if (c < 640){
                    v = *(const float4*)(g_agg + (size_t)r*512 + (c - 128));
                } else if (c < 1152){
                    v = *(const float4*)(g_agg + (size_t)r*512 + (c - 640));
                    float s = g_amp[r];
                    v.x *= s; v.y *= s; v.z *= s; v.w *= s;
                } else {
                    v = *(const float4*)(g_agg + (size_t)r*512 + (c - 1152));
                    float s = g_att[r];
                    v.x *= s; v.y *= s; v.z *= s; v.w *= s;
                }
            }
            ra[i] = v;
        }
    };
    auto storeA = [&](int buf){
        uint32_t* A = Asb[buf];
        #pragma unroll
        for (int i = 0; i < 4; i++){
            int idx = tid + 256*i;
            int rl  = idx >> 3, k4 = idx & 7;
            A[(k4*4+0)*132 + rl] = f2tf32(ra[i].x);
            A[(k4*4+1)*132 + rl] = f2tf32(ra[i].y);
            A[(k4*4+2)*132 + rl] = f2tf32(ra[i].z);
            A[(k4*4+3)*132 + rl] = f2tf32(ra[i].w);
        }
    };
    auto loadW = [&](int k0, int buf){
        uint32_t* W = Wsb[buf];
        #pragma unroll
        for (int i = 0; i < 4; i++){
            int idx = tid + 256*i;
            int k   = idx >> 5, n4 = idx & 31;
            uint32_t dstaddr = (uint32_t)__cvta_generic_to_shared(&W[k*132 + n4*4]);
            cp_async16(dstaddr, g_Wt_comb + (size_t)(k0+k)*128 + n4*4);
        }
    };

    const int T = KPOST/32;   // 52
    loadW(0, 0); CP_COMMIT();
    loadA(0); storeA(0);
    CP_WAIT0();
    __syncthreads();

    for (int t = 0; t < T; t++){
        int cur = t & 1, nxt = cur ^ 1;
        if (t + 1 < T){
            loadW((t+1)*32, nxt); CP_COMMIT();
            loadA((t+1)*32);
        }
        uint32_t* A = Asb[cur];
        uint32_t* W = Wsb[cur];
        #pragma unroll
        for (int ks = 0; ks < 4; ks++){
            int kk = ks*8;
            uint32_t a[2][4], b[8][2];
            #pragma unroll
            for (int mt = 0; mt < 2; mt++){
                int row = wm + mt*16 + grp;
                a[mt][0] = A[(kk+qid  )*132 + row];
                a[mt][1] = A[(kk+qid  )*132 + row+8];
                a[mt][2] = A[(kk+qid+4)*132 + row];
                a[mt][3] = A[(kk+qid+4)*132 + row+8];
            }
            #pragma unroll
            for (int nt = 0; nt < 8; nt++){
                int col = wn + nt*8 + grp;
                b[nt][0] = W[(kk+qid  )*132 + col];
                b[nt][1] = W[(kk+qid+4)*132 + col];
            }
            #pragma unroll
            for (int mt = 0; mt < 2; mt++)
                #pragma unroll
                for (int nt = 0; nt < 8; nt++){
                    asm volatile(
                        "mma.sync.aligned.m16n8k8.row.col.f32.tf32.tf32.f32 "
                        "{%0,%1,%2,%3}, {%4,%5,%6,%7}, {%8,%9}, {%0,%1,%2,%3};\n"
                        : "+f"(acc[mt][nt][0]), "+f"(acc[mt][nt][1]),
                          "+f"(acc[mt][nt][2]), "+f"(acc[mt][nt][3])
                        : "r"(a[mt][0]), "r"(a[mt][1]), "r"(a[mt][2]), "r"(a[mt][3]),
                          "r"(b[nt][0]), "r"(b[nt][1]));
                }
        }
        if (t + 1 < T){
            storeA(nxt);
            CP_WAIT0();
        }
        __syncthreads();
    }

    #pragma unroll
    for (int mt = 0; mt < 2; mt++){
        int row0 = m0 + wm + mt*16 + grp;
        #pragma unroll
        for (int nt = 0; nt < 8; nt++){
            int col = wn + nt*8 + 2*qid;
            float b0 = g_b_comb[col], b1 = g_b_comb[col+1];
            if (row0 < M){
                float2 v = make_float2(acc[mt][nt][0] + b0, acc[mt][nt][1] + b1);
                *(float2*)(C + (size_t)row0*128 + col) = v;
            }
            if (row0 + 8 < M){
                float2 v = make_float2(acc[mt][nt][2] + b0, acc[mt][nt][3] + b1);
                *(float2*)(C + (size_t)(row0+8)*128 + col) = v;
            }
        }
    }
}

// ---------------- launch -----------------------------------------------------
extern "C" void kernel_launch(void* const* d_in, const int* in_sizes, int n_in,
                              void* d_out, int out_size)
{
    const float* x      = (const float*)d_in[0];
    const int*   ei     = (const int*)  d_in[1];
    const float* W_pre  = (const float*)d_in[2];
    const float* b_pre  = (const float*)d_in[3];
    const float* W_post = (const float*)d_in[4];
    const float* b_post = (const float*)d_in[5];
    const float* W_lin  = (const float*)d_in[6];
    const float* b_lin  = (const float*)d_in[7];
    float* out = (float*)d_out;

    int N = in_sizes[0] / FDIM;
    int E = in_sizes[1] / 2;
    const int* src = ei;        // edge_index[0] = x_j (source)
    const int* dst = ei + E;    // edge_index[1] = x_i (destination)

    cudaFuncSetAttribute(k_post_tf32,
                         cudaFuncAttributeMaxDynamicSharedMemorySize,
                         POST_SMEM_BYTES);

    // CSR build
    k_zero   <<<(N+255)/256, 256>>>(N);
    k_hist   <<<(E+255)/256, 256>>>(dst, E);
    k_scan   <<<1, 1024>>>(N);
    k_scatter<<<(E+255)/256, 256>>>(src, dst, E);

    // weight prep
    k_prep_uv<<<128, 256>>>(W_pre);
    k_transpose_lin<<<64, 256>>>(W_lin);
    k_combine<<<KPOST, FDIM>>>(W_post);
    k_bias<<<1, FDIM>>>(b_post, b_lin);

    // fused u/v tf32 GEMM
    int gm = (N + 127) / 128;
    dim3 guv(gm, 2);
    k_uv_tf32<<<guv, 256>>>(x, N, b_pre);

    // segment aggregation (max/min/mean/std) + scalers
    k_agg<<<N, FDIM>>>(N);

    // fused tf32 tensor-core post GEMM (double-buffered, dynamic smem)
    k_post_tf32<<<gm, 256, POST_SMEM_BYTES>>>(x, N, out);
}

// round 6
// speedup vs baseline: 2.2792x; 1.1292x over previous
#include <cuda_runtime.h>
#include <math.h>
#include <stdint.h>

#define FDIM 128
#define NMAX 50000
#define NPAD (NMAX + 128)
#define EMAX 800000
#define KPOST (13*FDIM)   /* 1664 */

// ---------------- scratch (static device globals; no allocation) -------------
__device__ __align__(16) int   g_deg[NMAX];
__device__ __align__(16) int   g_rowptr[NMAX+1];
__device__ __align__(16) int   g_cursor[NMAX];
__device__ __align__(16) int   g_srcs[EMAX];
__device__ __align__(16) float g_u[(size_t)NMAX*FDIM];
__device__ __align__(16) float g_v[(size_t)NMAX*FDIM];
__device__ __align__(16) float g_A[(size_t)NPAD*KPOST];        // [N][1664] tf32-rounded
__device__ __align__(16) float g_Wt_uv[128*256];               // [k][256], tf32-rounded
__device__ __align__(16) float g_Wt_lin[FDIM*FDIM];            // [128][128] (k-major)
__device__ __align__(16) float g_Wt_comb[(size_t)KPOST*FDIM];  // [k=1664][n=128], tf32-rounded
__device__ __align__(16) float g_b_comb[FDIM];

__device__ __forceinline__ uint32_t f2tf32(float f){
    uint32_t r;
    asm("cvt.rna.tf32.f32 %0, %1;" : "=r"(r) : "f"(f));
    return r;
}
__device__ __forceinline__ float tf32f(float f){ return __uint_as_float(f2tf32(f)); }
__device__ __forceinline__ uint32_t s2u(const void* p){
    return (uint32_t)__cvta_generic_to_shared(p);
}
__device__ __forceinline__ void cp_async16(uint32_t smem, const void* gmem){
    asm volatile("cp.async.cg.shared.global [%0], [%1], 16;\n" :: "r"(smem), "l"(gmem));
}
#define CP_COMMIT() asm volatile("cp.async.commit_group;\n" ::: "memory")
#define CP_WAIT0()  asm volatile("cp.async.wait_group 0;\n" ::: "memory")
#define CP_WAIT1()  asm volatile("cp.async.wait_group 1;\n" ::: "memory")

// ---------------- CSR build --------------------------------------------------
__global__ void k_zero(int n){
    int i = blockIdx.x*blockDim.x + threadIdx.x;
    if (i < n) g_deg[i] = 0;
}

__global__ void k_hist(const int* __restrict__ dst, int E){
    int e = blockIdx.x*blockDim.x + threadIdx.x;
    if (e < E) atomicAdd(&g_deg[dst[e]], 1);
}

__global__ void k_scan(int n){
    __shared__ int ss[1024];
    int t = threadIdx.x;
    int chunk = (n + 1023) >> 10;
    int lo = t*chunk;
    int hi = min(lo + chunk, n);
    int s = 0;
    for (int i = lo; i < hi; i++) s += g_deg[i];
    ss[t] = s;
    __syncthreads();
    for (int off = 1; off < 1024; off <<= 1){
        int v = (t >= off) ? ss[t-off] : 0;
        __syncthreads();
        ss[t] += v;
        __syncthreads();
    }
    int run = (t == 0) ? 0 : ss[t-1];
    for (int i = lo; i < hi; i++){
        g_rowptr[i] = run;
        g_cursor[i] = run;
        run += g_deg[i];
    }
    if (t == 1023) g_rowptr[n] = ss[1023];
}

__global__ void k_scatter(const int* __restrict__ src, const int* __restrict__ dst, int E){
    int e = blockIdx.x*blockDim.x + threadIdx.x;
    if (e < E){
        int d = dst[e];
        int p = atomicAdd(&g_cursor[d], 1);
        g_srcs[p] = src[e];
    }
}

// ---------------- weight prep ------------------------------------------------
__global__ void k_prep_uv(const float* __restrict__ W_pre){
    int idx = blockIdx.x*256 + threadIdx.x;
    if (idx < 128*256){
        int k = idx >> 8, j = idx & 255;
        float val = W_pre[(size_t)(j & 127)*256 + ((j >> 7) ? (128 + k) : k)];
        g_Wt_uv[idx] = tf32f(val);
    }
}

__global__ void k_transpose_lin(const float* __restrict__ in){
    int idx = blockIdx.x*256 + threadIdx.x;
    if (idx < FDIM*FDIM){
        int f = idx >> 7, c = idx & 127;
        g_Wt_lin[c*FDIM + f] = in[idx];
    }
}

// Wt_comb[c=k][f=n] = sum_j W_lin[f][j] * W_post[j][c], rounded to tf32
__global__ void k_combine(const float* __restrict__ W_post){
    int c = blockIdx.x;
    int f = threadIdx.x;
    __shared__ float col[FDIM];
    col[f] = W_post[(size_t)f*KPOST + c];
    __syncthreads();
    float s = 0.f;
    #pragma unroll 8
    for (int k = 0; k < FDIM; k++)
        s = fmaf(g_Wt_lin[k*FDIM + f], col[k], s);
    g_Wt_comb[(size_t)c*FDIM + f] = tf32f(s);
}

__global__ void k_bias(const float* __restrict__ b_post, const float* __restrict__ b_lin){
    int f = threadIdx.x;
    float s = b_lin[f];
    #pragma unroll 8
    for (int k = 0; k < FDIM; k++)
        s = fmaf(g_Wt_lin[k*FDIM + f], b_post[k], s);
    g_b_comb[f] = s;
}

// ---------------- fused u/v TF32 GEMM: [u|v] = x @ Wuv  (K=128) --------------
__global__ void __launch_bounds__(256)
k_uv_tf32(const float* __restrict__ x, int M, const float* __restrict__ b_pre)
{
    __shared__ uint32_t As[32][132];
    __shared__ uint32_t Ws[32][132];
    int tid  = threadIdx.x;
    int m0   = blockIdx.x * 128;
    int half = blockIdx.y;
    float* Cout = half ? g_v : g_u;
    int wid  = tid >> 5, lane = tid & 31;
    int wm   = (wid >> 1) * 32;
    int wn   = (wid & 1) * 64;
    int grp  = lane >> 2, qid = lane & 3;

    float acc[2][8][4];
    #pragma unroll
    for (int mt = 0; mt < 2; mt++)
        #pragma unroll
        for (int nt = 0; nt < 8; nt++)
            #pragma unroll
            for (int q = 0; q < 4; q++) acc[mt][nt][q] = 0.f;

    for (int k0 = 0; k0 < 128; k0 += 32){
        #pragma unroll
        for (int i = 0; i < 4; i++){
            int idx = tid + 256*i;
            int rl  = idx >> 3, k4 = idx & 7;
            int r   = m0 + rl;
            float4 v = make_float4(0.f,0.f,0.f,0.f);
            if (r < M) v = *(const float4*)(x + (size_t)r*128 + k0 + k4*4);
            As[k4*4+0][rl] = f2tf32(v.x);
            As[k4*4+1][rl] = f2tf32(v.y);
            As[k4*4+2][rl] = f2tf32(v.z);
            As[k4*4+3][rl] = f2tf32(v.w);
        }
        #pragma unroll
        for (int i = 0; i < 4; i++){
            int idx = tid + 256*i;
            int k   = idx >> 5, n4 = idx & 31;
            float4 w = *(const float4*)(g_Wt_uv + (size_t)(k0+k)*256 + half*128 + n4*4);
            Ws[k][n4*4+0] = __float_as_uint(w.x);
            Ws[k][n4*4+1] = __float_as_uint(w.y);
            Ws[k][n4*4+2] = __float_as_uint(w.z);
            Ws[k][n4*4+3] = __float_as_uint(w.w);
        }
        __syncthreads();
        #pragma unroll
        for (int ks = 0; ks < 4; ks++){
            int kk = ks*8;
            uint32_t a[2][4], b[8][2];
            #pragma unroll
            for (int mt = 0; mt < 2; mt++){
                int row = wm + mt*16 + grp;
                a[mt][0] = As[kk+qid  ][row];
                a[mt][1] = As[kk+qid  ][row+8];
                a[mt][2] = As[kk+qid+4][row];
                a[mt][3] = As[kk+qid+4][row+8];
            }
            #pragma unroll
            for (int nt = 0; nt < 8; nt++){
                int col = wn + nt*8 + grp;
                b[nt][0] = Ws[kk+qid  ][col];
                b[nt][1] = Ws[kk+qid+4][col];
            }
            #pragma unroll
            for (int mt = 0; mt < 2; mt++)
                #pragma unroll
                for (int nt = 0; nt < 8; nt++){
                    asm volatile(
                        "mma.sync.aligned.m16n8k8.row.col.f32.tf32.tf32.f32 "
                        "{%0,%1,%2,%3}, {%4,%5,%6,%7}, {%8,%9}, {%0,%1,%2,%3};\n"
                        : "+f"(acc[mt][nt][0]), "+f"(acc[mt][nt][1]),
                          "+f"(acc[mt][nt][2]), "+f"(acc[mt][nt][3])
                        : "r"(a[mt][0]), "r"(a[mt][1]), "r"(a[mt][2]), "r"(a[mt][3]),
                          "r"(b[nt][0]), "r"(b[nt][1]));
                }
        }
        __syncthreads();
    }

    #pragma unroll
    for (int mt = 0; mt < 2; mt++){
        int row0 = m0 + wm + mt*16 + grp;
        #pragma unroll
        for (int nt = 0; nt < 8; nt++){
            int col = wn + nt*8 + 2*qid;
            float b0 = half ? 0.f : b_pre[col];
            float b1 = half ? 0.f : b_pre[col+1];
            if (row0 < M){
                float2 v = make_float2(acc[mt][nt][0] + b0, acc[mt][nt][1] + b1);
                *(float2*)(Cout + (size_t)row0*128 + col) = v;
            }
            if (row0 + 8 < M){
                float2 v = make_float2(acc[mt][nt][2] + b0, acc[mt][nt][3] + b1);
                *(float2*)(Cout + (size_t)(row0+8)*128 + col) = v;
            }
        }
    }
}

// ---------------- per-node aggregation; writes full A row --------------------
// g_A[node][0:128)=x, [128:640)=agg, [640:1152)=agg*amp, [1152:1664)=agg*att
__global__ void k_agg(const float* __restrict__ x, int n){
    int node = blockIdx.x;
    int f = threadIdx.x;
    int s0 = g_rowptr[node], s1 = g_rowptr[node+1];
    float uf = g_u[(size_t)node*FDIM + f];
    float mx = -3.402823466e38f, mn = 3.402823466e38f, sm = 0.f, sq = 0.f;
    int e = s0;
    for (; e + 3 < s1; e += 4){
        int i0 = g_srcs[e], i1 = g_srcs[e+1], i2 = g_srcs[e+2], i3 = g_srcs[e+3];
        float v0 = g_v[(size_t)i0*FDIM + f];
        float v1 = g_v[(size_t)i1*FDIM + f];
        float v2 = g_v[(size_t)i2*FDIM + f];
        float v3 = g_v[(size_t)i3*FDIM + f];
        float a0 = uf + v0, a1 = uf + v1, a2 = uf + v2, a3 = uf + v3;
        mx = fmaxf(mx, fmaxf(fmaxf(a0, a1), fmaxf(a2, a3)));
        mn = fminf(mn, fminf(fminf(a0, a1), fminf(a2, a3)));
        sm += a0 + a1 + a2 + a3;
        sq = fmaf(a0, a0, sq); sq = fmaf(a1, a1, sq);
        sq = fmaf(a2, a2, sq); sq = fmaf(a3, a3, sq);
    }
    for (; e < s1; e++){
        int s = g_srcs[e];
        float val = uf + g_v[(size_t)s*FDIM + f];
        mx = fmaxf(mx, val);
        mn = fminf(mn, val);
        sm += val;
        sq = fmaf(val, val, sq);
    }
    int deg = s1 - s0;
    if (deg == 0){ mx = 0.f; mn = 0.f; }
    float dc   = fmaxf((float)deg, 1.f);
    float mean = sm / dc;
    float var  = sq / dc - mean*mean;
    float sd   = sqrtf(fmaxf(var, 0.f) + 1e-5f);
    float ld   = logf(dc + 1.f);     // DELTA = 1.0
    float amp  = ld;
    float att  = 1.f / ld;

    size_t b = (size_t)node * KPOST;
    g_A[b + f]            = tf32f(x[(size_t)node*FDIM + f]);
    g_A[b + 128  + f]     = tf32f(mx);
    g_A[b + 256  + f]     = tf32f(mn);
    g_A[b + 384  + f]     = tf32f(mean);
    g_A[b + 512  + f]     = tf32f(sd);
    g_A[b + 640  + f]     = tf32f(mx*amp);
    g_A[b + 768  + f]     = tf32f(mn*amp);
    g_A[b + 896  + f]     = tf32f(mean*amp);
    g_A[b + 1024 + f]     = tf32f(sd*amp);
    g_A[b + 1152 + f]     = tf32f(mx*att);
    g_A[b + 1280 + f]     = tf32f(mn*att);
    g_A[b + 1408 + f]     = tf32f(mean*att);
    g_A[b + 1536 + f]     = tf32f(sd*att);
}

// ---------------- TF32 post GEMM, K=1664, cp.async double-buffered -----------
// As: [2][128][36] row-major (pad 36 -> conflict-free frags), Ws: [2][32][132]
#define AS_F (128*36)
#define WS_F (32*132)
#define POST_SMEM_BYTES ((2*AS_F + 2*WS_F)*4)

__global__ void __launch_bounds__(256, 2)
k_post_tf32(int M, float* __restrict__ C)
{
    extern __shared__ float smf[];
    float* Asb[2] = { smf,           smf + AS_F };
    float* Wsb[2] = { smf + 2*AS_F,  smf + 2*AS_F + WS_F };

    int tid  = threadIdx.x;
    int m0   = blockIdx.x * 128;
    int wid  = tid >> 5, lane = tid & 31;
    int wm   = (wid >> 1) * 32;
    int wn   = (wid & 1) * 64;
    int grp  = lane >> 2, qid = lane & 3;

    float acc[2][8][4];
    #pragma unroll
    for (int mt = 0; mt < 2; mt++)
        #pragma unroll
        for (int nt = 0; nt < 8; nt++)
            #pragma unroll
            for (int q = 0; q < 4; q++) acc[mt][nt][q] = 0.f;

    const float* Abase = g_A + (size_t)m0*KPOST;

    auto loadTile = [&](int t, int buf){
        float* A = Asb[buf];
        const float* Ag = Abase + t*32;
        #pragma unroll
        for (int i = 0; i < 4; i++){
            int idx = tid + 256*i;
            int rl  = idx >> 3, k4 = idx & 7;
            cp_async16(s2u(&A[rl*36 + k4*4]), Ag + (size_t)rl*KPOST + k4*4);
        }
        float* W = Wsb[buf];
        const float* Wg = g_Wt_comb + (size_t)t*32*128;
        #pragma unroll
        for (int i = 0; i < 4; i++){
            int idx = tid + 256*i;
            int k   = idx >> 5, n4 = idx & 31;
            cp_async16(s2u(&W[k*132 + n4*4]), Wg + (size_t)k*128 + n4*4);
        }
    };

    const int T = KPOST/32;   // 52
    loadTile(0, 0); CP_COMMIT();
    loadTile(1, 1); CP_COMMIT();
    CP_WAIT1();
    __syncthreads();

    for (int t = 0; t < T; t++){
        int cur = t & 1;
        float* A = Asb[cur];
        float* W = Wsb[cur];
        #pragma unroll
        for (int ks = 0; ks < 4; ks++){
            int kk = ks*8;
            uint32_t a[2][4], b[8][2];
            #pragma unroll
            for (int mt = 0; mt < 2; mt++){
                int row = wm + mt*16 + grp;
                a[mt][0] = __float_as_uint(A[row*36     + kk+qid  ]);
                a[mt][1] = __float_as_uint(A[(row+8)*36 + kk+qid  ]);
                a[mt][2] = __float_as_uint(A[row*36     + kk+qid+4]);
                a[mt][3] = __float_as_uint(A[(row+8)*36 + kk+qid+4]);
            }
            #pragma unroll
            for (int nt = 0; nt < 8; nt++){
                int col = wn + nt*8 + grp;
                b[nt][0] = __float_as_uint(W[(kk+qid  )*132 + col]);
                b[nt][1] = __float_as_uint(W[(kk+qid+4)*132 + col]);
            }
            #pragma unroll
            for (int mt = 0; mt < 2; mt++)
                #pragma unroll
                for (int nt = 0; nt < 8; nt++){
                    asm volatile(
                        "mma.sync.aligned.m16n8k8.row.col.f32.tf32.tf32.f32 "
                        "{%0,%1,%2,%3}, {%4,%5,%6,%7}, {%8,%9}, {%0,%1,%2,%3};\n"
                        : "+f"(acc[mt][nt][0]), "+f"(acc[mt][nt][1]),
                          "+f"(acc[mt][nt][2]), "+f"(acc[mt][nt][3])
                        : "r"(a[mt][0]), "r"(a[mt][1]), "r"(a[mt][2]), "r"(a[mt][3]),
                          "r"(b[nt][0]), "r"(b[nt][1]));
                }
        }
        __syncthreads();                 // all warps done reading buffer cur
        if (t + 2 < T){
            loadTile(t + 2, cur); CP_COMMIT();
            CP_WAIT1();                  // tile t+1 complete (t+2 may be in flight)
            __syncthreads();
        } else if (t + 1 < T){
            CP_WAIT0();                  // only tile t+1 pending
            __syncthreads();
        }
    }

    #pragma unroll
    for (int mt = 0; mt < 2; mt++){
        int row0 = m0 + wm + mt*16 + grp;
        #pragma unroll
        for (int nt = 0; nt < 8; nt++){
            int col = wn + nt*8 + 2*qid;
            float b0 = g_b_comb[col], b1 = g_b_comb[col+1];
            if (row0 < M){
                float2 v = make_float2(acc[mt][nt][0] + b0, acc[mt][nt][1] + b1);
                *(float2*)(C + (size_t)row0*128 + col) = v;
            }
            if (row0 + 8 < M){
                float2 v = make_float2(acc[mt][nt][2] + b0, acc[mt][nt][3] + b1);
                *(float2*)(C + (size_t)(row0+8)*128 + col) = v;
            }
        }
    }
}

// ---------------- launch -----------------------------------------------------
extern "C" void kernel_launch(void* const* d_in, const int* in_sizes, int n_in,
                              void* d_out, int out_size)
{
    const float* x      = (const float*)d_in[0];
    const int*   ei     = (const int*)  d_in[1];
    const float* W_pre  = (const float*)d_in[2];
    const float* b_pre  = (const float*)d_in[3];
    const float* W_post = (const float*)d_in[4];
    const float* b_post = (const float*)d_in[5];
    const float* W_lin  = (const float*)d_in[6];
    const float* b_lin  = (const float*)d_in[7];
    float* out = (float*)d_out;

    int N = in_sizes[0] / FDIM;
    int E = in_sizes[1] / 2;
    const int* src = ei;        // edge_index[0] = x_j (source)
    const int* dst = ei + E;    // edge_index[1] = x_i (destination)

    cudaFuncSetAttribute(k_post_tf32,
                         cudaFuncAttributeMaxDynamicSharedMemorySize,
                         POST_SMEM_BYTES);

    // CSR build
    k_zero   <<<(N+255)/256, 256>>>(N);
    k_hist   <<<(E+255)/256, 256>>>(dst, E);
    k_scan   <<<1, 1024>>>(N);
    k_scatter<<<(E+255)/256, 256>>>(src, dst, E);

    // weight prep
    k_prep_uv<<<128, 256>>>(W_pre);
    k_transpose_lin<<<64, 256>>>(W_lin);
    k_combine<<<KPOST, FDIM>>>(W_post);
    k_bias<<<1, FDIM>>>(b_post, b_lin);

    // fused u/v tf32 GEMM
    int gm = (N + 127) / 128;
    dim3 guv(gm, 2);
    k_uv_tf32<<<guv, 256>>>(x, N, b_pre);

    // aggregation + full A materialization (pre-scaled, tf32-rounded)
    k_agg<<<N, FDIM>>>(x, N);

    // clean tf32 post GEMM (cp.async double-buffered, 2 CTAs/SM)
    k_post_tf32<<<gm, 256, POST_SMEM_BYTES>>>(N, out);
}

// round 7
// speedup vs baseline: 2.7081x; 1.1882x over previous
#include <cuda_runtime.h>
#include <math.h>
#include <stdint.h>

#define FDIM 128
#define NMAX 50000
#define NPAD (NMAX + 128)
#define EMAX 800000
#define KPOST (13*FDIM)   /* 1664 */

// ---------------- scratch (static device globals; no allocation) -------------
__device__ __align__(16) int   g_deg[NMAX];
__device__ __align__(16) int   g_rowptr[NMAX+1];
__device__ __align__(16) int   g_cursor[NMAX];
__device__ __align__(16) int   g_srcs[EMAX];
__device__ __align__(16) float g_u[(size_t)NMAX*FDIM];
__device__ __align__(16) float g_v[(size_t)NMAX*FDIM];
__device__ __align__(16) float g_agg[(size_t)NPAD*4*FDIM];     // [NPAD][512] tf32-rounded
__device__ __align__(16) float g_amp[NMAX];
__device__ __align__(16) float g_att[NMAX];
__device__ __align__(16) float g_Wt_uv[128*256];               // [k][256], tf32-rounded
__device__ __align__(16) float g_Wt_lin[FDIM*FDIM];            // [128][128] (k-major)
__device__ __align__(16) float g_Wt_comb[(size_t)KPOST*FDIM];  // [k=1664][n=128], tf32-rounded
__device__ __align__(16) float g_b_comb[FDIM];

__device__ __forceinline__ uint32_t f2tf32(float f){
    uint32_t r;
    asm("cvt.rna.tf32.f32 %0, %1;" : "=r"(r) : "f"(f));
    return r;
}
__device__ __forceinline__ float tf32f(float f){ return __uint_as_float(f2tf32(f)); }
__device__ __forceinline__ uint32_t s2u(const void* p){
    return (uint32_t)__cvta_generic_to_shared(p);
}
__device__ __forceinline__ void cp_async16(uint32_t smem, const void* gmem){
    asm volatile("cp.async.cg.shared.global [%0], [%1], 16;\n" :: "r"(smem), "l"(gmem));
}
#define CP_COMMIT() asm volatile("cp.async.commit_group;\n" ::: "memory")
#define CP_WAIT0()  asm volatile("cp.async.wait_group 0;\n" ::: "memory")
#define CP_WAIT1()  asm volatile("cp.async.wait_group 1;\n" ::: "memory")

#define MMA_TF32(acc, a0,a1,a2,a3, b0,b1) \
    asm volatile( \
        "mma.sync.aligned.m16n8k8.row.col.f32.tf32.tf32.f32 " \
        "{%0,%1,%2,%3}, {%4,%5,%6,%7}, {%8,%9}, {%0,%1,%2,%3};\n" \
        : "+f"((acc)[0]), "+f"((acc)[1]), "+f"((acc)[2]), "+f"((acc)[3]) \
        : "r"(a0), "r"(a1), "r"(a2), "r"(a3), "r"(b0), "r"(b1))

// ---------------- CSR build --------------------------------------------------
__global__ void k_zero(int n){
    int i = blockIdx.x*blockDim.x + threadIdx.x;
    if (i < n) g_deg[i] = 0;
}

__global__ void k_hist(const int* __restrict__ dst, int E){
    int e = blockIdx.x*blockDim.x + threadIdx.x;
    if (e < E) atomicAdd(&g_deg[dst[e]], 1);
}

__global__ void k_scan(int n){
    __shared__ int ss[1024];
    int t = threadIdx.x;
    int chunk = (n + 1023) >> 10;
    int lo = t*chunk;
    int hi = min(lo + chunk, n);
    int s = 0;
    for (int i = lo; i < hi; i++) s += g_deg[i];
    ss[t] = s;
    __syncthreads();
    for (int off = 1; off < 1024; off <<= 1){
        int v = (t >= off) ? ss[t-off] : 0;
        __syncthreads();
        ss[t] += v;
        __syncthreads();
    }
    int run = (t == 0) ? 0 : ss[t-1];
    for (int i = lo; i < hi; i++){
        g_rowptr[i] = run;
        g_cursor[i] = run;
        run += g_deg[i];
    }
    if (t == 1023) g_rowptr[n] = ss[1023];
}

__global__ void k_scatter(const int* __restrict__ src, const int* __restrict__ dst, int E){
    int e = blockIdx.x*blockDim.x + threadIdx.x;
    if (e < E){
        int d = dst[e];
        int p = atomicAdd(&g_cursor[d], 1);
        g_srcs[p] = src[e];
    }
}

// ---------------- weight prep ------------------------------------------------
__global__ void k_prep_uv(const float* __restrict__ W_pre){
    int idx = blockIdx.x*256 + threadIdx.x;
    if (idx < 128*256){
        int k = idx >> 8, j = idx & 255;
        float val = W_pre[(size_t)(j & 127)*256 + ((j >> 7) ? (128 + k) : k)];
        g_Wt_uv[idx] = tf32f(val);
    }
}

__global__ void k_transpose_lin(const float* __restrict__ in){
    int idx = blockIdx.x*256 + threadIdx.x;
    if (idx < FDIM*FDIM){
        int f = idx >> 7, c = idx & 127;
        g_Wt_lin[c*FDIM + f] = in[idx];
    }
}

// Wt_comb[c=k][f=n] = sum_j W_lin[f][j] * W_post[j][c], rounded to tf32
__global__ void k_combine(const float* __restrict__ W_post){
    int c = blockIdx.x;
    int f = threadIdx.x;
    __shared__ float col[FDIM];
    col[f] = W_post[(size_t)f*KPOST + c];
    __syncthreads();
    float s = 0.f;
    #pragma unroll 8
    for (int k = 0; k < FDIM; k++)
        s = fmaf(g_Wt_lin[k*FDIM + f], col[k], s);
    g_Wt_comb[(size_t)c*FDIM + f] = tf32f(s);
}

__global__ void k_bias(const float* __restrict__ b_post, const float* __restrict__ b_lin){
    int f = threadIdx.x;
    float s = b_lin[f];
    #pragma unroll 8
    for (int k = 0; k < FDIM; k++)
        s = fmaf(g_Wt_lin[k*FDIM + f], b_post[k], s);
    g_b_comb[f] = s;
}

// ---------------- u/v TF32 GEMM, cp.async double-buffered (K=128) ------------
// gridDim.y: 0 -> u (bias b_pre), 1 -> v (no bias). A = raw x (HW tf32 truncation).
#define UV_AS (128*36)
#define UV_WS (32*132)
#define UV_SMEM_BYTES ((2*UV_AS + 2*UV_WS)*4)

__global__ void __launch_bounds__(256, 2)
k_uv_tf32(const float* __restrict__ x, int M, const float* __restrict__ b_pre)
{
    extern __shared__ float smf[];
    float* Asb[2] = { smf,            smf + UV_AS };
    float* Wsb[2] = { smf + 2*UV_AS,  smf + 2*UV_AS + UV_WS };

    int tid  = threadIdx.x;
    int m0   = blockIdx.x * 128;
    int half = blockIdx.y;
    float* Cout = half ? g_v : g_u;
    int wid  = tid >> 5, lane = tid & 31;
    int wm   = (wid >> 1) * 32;
    int wn   = (wid & 1) * 64;
    int grp  = lane >> 2, qid = lane & 3;

    float acc[2][8][4];
    #pragma unroll
    for (int mt = 0; mt < 2; mt++)
        #pragma unroll
        for (int nt = 0; nt < 8; nt++)
            #pragma unroll
            for (int q = 0; q < 4; q++) acc[mt][nt][q] = 0.f;

    auto loadTile = [&](int t, int buf){
        float* A = Asb[buf];
        #pragma unroll
        for (int i = 0; i < 4; i++){
            int idx = tid + 256*i;
            int rl  = idx >> 3, k4 = idx & 7;
            int r   = m0 + rl; if (r >= M) r = M - 1;
            cp_async16(s2u(&A[rl*36 + k4*4]), x + (size_t)r*128 + t*32 + k4*4);
        }
        float* W = Wsb[buf];
        #pragma unroll
        for (int i = 0; i < 4; i++){
            int idx = tid + 256*i;
            int k   = idx >> 5, n4 = idx & 31;
            cp_async16(s2u(&W[k*132 + n4*4]),
                       g_Wt_uv + (size_t)(t*32+k)*256 + half*128 + n4*4);
        }
    };

    const int T = 4;
    loadTile(0, 0); CP_COMMIT();
    loadTile(1, 1); CP_COMMIT();
    CP_WAIT1();
    __syncthreads();

    for (int t = 0; t < T; t++){
        int cur = t & 1;
        float* A = Asb[cur];
        float* W = Wsb[cur];
        #pragma unroll
        for (int ks = 0; ks < 4; ks++){
            int kk = ks*8;
            uint32_t a[2][4], b[8][2];
            #pragma unroll
            for (int mt = 0; mt < 2; mt++){
                int row = wm + mt*16 + grp;
                a[mt][0] = __float_as_uint(A[row*36     + kk+qid  ]);
                a[mt][1] = __float_as_uint(A[(row+8)*36 + kk+qid  ]);
                a[mt][2] = __float_as_uint(A[row*36     + kk+qid+4]);
                a[mt][3] = __float_as_uint(A[(row+8)*36 + kk+qid+4]);
            }
            #pragma unroll
            for (int nt = 0; nt < 8; nt++){
                int col = wn + nt*8 + grp;
                b[nt][0] = __float_as_uint(W[(kk+qid  )*132 + col]);
                b[nt][1] = __float_as_uint(W[(kk+qid+4)*132 + col]);
            }
            #pragma unroll
            for (int mt = 0; mt < 2; mt++)
                #pragma unroll
                for (int nt = 0; nt < 8; nt++)
                    MMA_TF32(acc[mt][nt], a[mt][0],a[mt][1],a[mt][2],a[mt][3],
                             b[nt][0], b[nt][1]);
        }
        __syncthreads();
        if (t + 2 < T){
            loadTile(t + 2, cur); CP_COMMIT();
            CP_WAIT1();
            __syncthreads();
        } else if (t + 1 < T){
            CP_WAIT0();
            __syncthreads();
        }
    }

    #pragma unroll
    for (int mt = 0; mt < 2; mt++){
        int row0 = m0 + wm + mt*16 + grp;
        #pragma unroll
        for (int nt = 0; nt < 8; nt++){
            int col = wn + nt*8 + 2*qid;
            float b0 = half ? 0.f : b_pre[col];
            float b1 = half ? 0.f : b_pre[col+1];
            if (row0 < M){
                float2 v = make_float2(acc[mt][nt][0] + b0, acc[mt][nt][1] + b1);
                *(float2*)(Cout + (size_t)row0*128 + col) = v;
            }
            if (row0 + 8 < M){
                float2 v = make_float2(acc[mt][nt][2] + b0, acc[mt][nt][3] + b1);
                *(float2*)(Cout + (size_t)(row0+8)*128 + col) = v;
            }
        }
    }
}

// ---------------- per-node aggregation over CSR ------------------------------
__global__ void k_agg(int n){
    int node = blockIdx.x;
    int f = threadIdx.x;
    int s0 = g_rowptr[node], s1 = g_rowptr[node+1];
    float uf = g_u[(size_t)node*FDIM + f];
    float mx = -3.402823466e38f, mn = 3.402823466e38f, sm = 0.f, sq = 0.f;
    int e = s0;
    for (; e + 3 < s1; e += 4){
        int i0 = g_srcs[e], i1 = g_srcs[e+1], i2 = g_srcs[e+2], i3 = g_srcs[e+3];
        float v0 = g_v[(size_t)i0*FDIM + f];
        float v1 = g_v[(size_t)i1*FDIM + f];
        float v2 = g_v[(size_t)i2*FDIM + f];
        float v3 = g_v[(size_t)i3*FDIM + f];
        float a0 = uf + v0, a1 = uf + v1, a2 = uf + v2, a3 = uf + v3;
        mx = fmaxf(mx, fmaxf(fmaxf(a0, a1), fmaxf(a2, a3)));
        mn = fminf(mn, fminf(fminf(a0, a1), fminf(a2, a3)));
        sm += a0 + a1 + a2 + a3;
        sq = fmaf(a0, a0, sq); sq = fmaf(a1, a1, sq);
        sq = fmaf(a2, a2, sq); sq = fmaf(a3, a3, sq);
    }
    for (; e < s1; e++){
        int s = g_srcs[e];
        float val = uf + g_v[(size_t)s*FDIM + f];
        mx = fmaxf(mx, val);
        mn = fminf(mn, val);
        sm += val;
        sq = fmaf(val, val, sq);
    }
    int deg = s1 - s0;
    if (deg == 0){ mx = 0.f; mn = 0.f; }
    float dc   = fmaxf((float)deg, 1.f);
    float mean = sm / dc;
    float var  = sq / dc - mean*mean;
    float sd   = sqrtf(fmaxf(var, 0.f) + 1e-5f);
    size_t b = (size_t)node * (4*FDIM);
    g_agg[b + f]          = tf32f(mx);
    g_agg[b + FDIM + f]   = tf32f(mn);
    g_agg[b + 2*FDIM + f] = tf32f(mean);
    g_agg[b + 3*FDIM + f] = tf32f(sd);
    if (f == 0){
        float ld = logf(dc + 1.f);   // DELTA = 1.0
        g_amp[node] = ld;
        g_att[node] = 1.f / ld;
    }
}

// ---------------- factored TF32 post GEMM ------------------------------------
// out = x@W0 + agg@W1 + amp.*(agg@W2) + att.*(agg@W3) + b_comb
// 3 register accumulator sets; each agg tile loaded once, used against 3 W slots.
#define P_AS (128*36)
#define P_WS (32*132)
#define P_STAGEF (P_AS + 3*P_WS)
#define POST_SMEM_BYTES (2*P_STAGEF*4)

__global__ void __launch_bounds__(256, 1)
k_post3(const float* __restrict__ x, int M, float* __restrict__ C)
{
    extern __shared__ float smf[];

    int tid  = threadIdx.x;
    int m0   = blockIdx.x * 128;
    int wid  = tid >> 5, lane = tid & 31;
    int wm   = (wid >> 1) * 32;
    int wn   = (wid & 1) * 64;
    int grp  = lane >> 2, qid = lane & 3;

    float accC[2][8][4], accA[2][8][4], accT[2][8][4];
    #pragma unroll
    for (int mt = 0; mt < 2; mt++)
        #pragma unroll
        for (int nt = 0; nt < 8; nt++)
            #pragma unroll
            for (int q = 0; q < 4; q++){
                accC[mt][nt][q] = 0.f; accA[mt][nt][q] = 0.f; accT[mt][nt][q] = 0.f;
            }

    auto loadTile = [&](int t, int buf){
        float* S = smf + buf*P_STAGEF;
        float* A = S;
        if (t < 4){
            int kc = t*32;
            #pragma unroll
            for (int i = 0; i < 4; i++){
                int idx = tid + 256*i;
                int rl  = idx >> 3, k4 = idx & 7;
                int r   = m0 + rl; if (r >= M) r = M - 1;
                cp_async16(s2u(&A[rl*36 + k4*4]), x + (size_t)r*128 + kc + k4*4);
            }
            float* W = S + P_AS;
            #pragma unroll
            for (int i = 0; i < 4; i++){
                int idx = tid + 256*i;
                int k   = idx >> 5, n4 = idx & 31;
                cp_async16(s2u(&W[k*132 + n4*4]),
                           g_Wt_comb + (size_t)(kc+k)*128 + n4*4);
            }
        } else {
            int ka = (t-4)*32;
            #pragma unroll
            for (int i = 0; i < 4; i++){
                int idx = tid + 256*i;
                int rl  = idx >> 3, k4 = idx & 7;
                cp_async16(s2u(&A[rl*36 + k4*4]),
                           g_agg + (size_t)(m0+rl)*512 + ka + k4*4);
            }
            const int OFF[3] = { 128, 640, 1152 };
            #pragma unroll
            for (int j = 0; j < 3; j++){
                float* W = S + P_AS + j*P_WS;
                #pragma unroll
                for (int i = 0; i < 4; i++){
                    int idx = tid + 256*i;
                    int k   = idx >> 5, n4 = idx & 31;
                    cp_async16(s2u(&W[k*132 + n4*4]),
                               g_Wt_comb + (size_t)(OFF[j]+ka+k)*128 + n4*4);
                }
            }
        }
    };

    const int T = 20;
    loadTile(0, 0); CP_COMMIT();
    loadTile(1, 1); CP_COMMIT();
    CP_WAIT1();
    __syncthreads();

    for (int t = 0; t < T; t++){
        int cur = t & 1;
        float* S = smf + cur*P_STAGEF;
        float* A = S;
        int nsets = (t < 4) ? 1 : 3;
        #pragma unroll
        for (int ks = 0; ks < 4; ks++){
            int kk = ks*8;
            uint32_t a[2][4];
            #pragma unroll
            for (int mt = 0; mt < 2; mt++){
                int row = wm + mt*16 + grp;
                a[mt][0] = __float_as_uint(A[row*36     + kk+qid  ]);
                a[mt][1] = __float_as_uint(A[(row+8)*36 + kk+qid  ]);
                a[mt][2] = __float_as_uint(A[row*36     + kk+qid+4]);
                a[mt][3] = __float_as_uint(A[(row+8)*36 + kk+qid+4]);
            }
            #pragma unroll
            for (int s = 0; s < 3; s++){
                if (s >= nsets) break;
                float* W = S + P_AS + s*P_WS;
                uint32_t b[8][2];
                #pragma unroll
                for (int nt = 0; nt < 8; nt++){
                    int col = wn + nt*8 + grp;
                    b[nt][0] = __float_as_uint(W[(kk+qid  )*132 + col]);
                    b[nt][1] = __float_as_uint(W[(kk+qid+4)*132 + col]);
                }
                float (*acc)[8][4] = (s == 0) ? accC : (s == 1) ? accA : accT;
                #pragma unroll
                for (int mt = 0; mt < 2; mt++)
                    #pragma unroll
                    for (int nt = 0; nt < 8; nt++)
                        MMA_TF32(acc[mt][nt], a[mt][0],a[mt][1],a[mt][2],a[mt][3],
                                 b[nt][0], b[nt][1]);
            }
        }
        __syncthreads();
        if (t + 2 < T){
            loadTile(t + 2, cur); CP_COMMIT();
            CP_WAIT1();
            __syncthreads();
        } else if (t + 1 < T){
            CP_WAIT0();
            __syncthreads();
        }
    }

    #pragma unroll
    for (int mt = 0; mt < 2; mt++){
        int row0 = m0 + wm + mt*16 + grp;
        int row1 = row0 + 8;
        float amp0 = 0.f, att0 = 0.f, amp1 = 0.f, att1 = 0.f;
        if (row0 < M){ amp0 = g_amp[row0]; att0 = g_att[row0]; }
        if (row1 < M){ amp1 = g_amp[row1]; att1 = g_att[row1]; }
        #pragma unroll
        for (int nt = 0; nt < 8; nt++){
            int col = wn + nt*8 + 2*qid;
            float b0 = g_b_comb[col], b1 = g_b_comb[col+1];
            if (row0 < M){
                float2 v;
                v.x = accC[mt][nt][0] + amp0*accA[mt][nt][0] + att0*accT[mt][nt][0] + b0;
                v.y = accC[mt][nt][1] + amp0*accA[mt][nt][1] + att0*accT[mt][nt][1] + b1;
                *(float2*)(C + (size_t)row0*128 + col) = v;
            }
            if (row1 < M){
                float2 v;
                v.x = accC[mt][nt][2] + amp1*accA[mt][nt][2] + att1*accT[mt][nt][2] + b0;
                v.y = accC[mt][nt][3] + amp1*accA[mt][nt][3] + att1*accT[mt][nt][3] + b1;
                *(float2*)(C + (size_t)row1*128 + col) = v;
            }
        }
    }
}

// ---------------- launch -----------------------------------------------------
extern "C" void kernel_launch(void* const* d_in, const int* in_sizes, int n_in,
                              void* d_out, int out_size)
{
    const float* x      = (const float*)d_in[0];
    const int*   ei     = (const int*)  d_in[1];
    const float* W_pre  = (const float*)d_in[2];
    const float* b_pre  = (const float*)d_in[3];
    const float* W_post = (const float*)d_in[4];
    const float* b_post = (const float*)d_in[5];
    const float* W_lin  = (const float*)d_in[6];
    const float* b_lin  = (const float*)d_in[7];
    float* out = (float*)d_out;

    int N = in_sizes[0] / FDIM;
    int E = in_sizes[1] / 2;
    const int* src = ei;        // edge_index[0] = x_j (source)
    const int* dst = ei + E;    // edge_index[1] = x_i (destination)

    cudaFuncSetAttribute(k_uv_tf32,
                         cudaFuncAttributeMaxDynamicSharedMemorySize, UV_SMEM_BYTES);
    cudaFuncSetAttribute(k_post3,
                         cudaFuncAttributeMaxDynamicSharedMemorySize, POST_SMEM_BYTES);

    // CSR build
    k_zero   <<<(N+255)/256, 256>>>(N);
    k_hist   <<<(E+255)/256, 256>>>(dst, E);
    k_scan   <<<1, 1024>>>(N);
    k_scatter<<<(E+255)/256, 256>>>(src, dst, E);

    // weight prep
    k_prep_uv<<<128, 256>>>(W_pre);
    k_transpose_lin<<<64, 256>>>(W_lin);
    k_combine<<<KPOST, FDIM>>>(W_post);
    k_bias<<<1, FDIM>>>(b_post, b_lin);

    // u/v tf32 GEMM (pipelined)
    int gm = (N + 127) / 128;
    dim3 guv(gm, 2);
    k_uv_tf32<<<guv, 256, UV_SMEM_BYTES>>>(x, N, b_pre);

    // aggregation (agg + amp/att only)
    k_agg<<<N, FDIM>>>(N);

    // factored tf32 post GEMM (3 accumulator sets)
    k_post3<<<gm, 256, POST_SMEM_BYTES>>>(x, N, out);
}

// round 8
// speedup vs baseline: 3.1307x; 1.1561x over previous
#include <cuda_runtime.h>
#include <cuda_fp16.h>
#include <math.h>
#include <stdint.h>

#define FDIM 128
#define NMAX 50000
#define NPAD (NMAX + 128)
#define EMAX 800000
#define KPOST (13*FDIM)   /* 1664 */

// ---------------- scratch (static device globals; no allocation) -------------
__device__ __align__(16) int    g_deg[NMAX];
__device__ __align__(16) int    g_rowptr[NMAX+1];
__device__ __align__(16) int    g_cursor[NMAX];
__device__ __align__(16) int    g_srcs[EMAX];
__device__ __align__(16) float  g_u[(size_t)NMAX*FDIM];
__device__ __align__(16) float  g_v[(size_t)NMAX*FDIM];
__device__ __align__(16) __half g_xh[(size_t)NPAD*FDIM];        // fp16 x
__device__ __align__(16) __half g_aggh[(size_t)NPAD*4*FDIM];    // [NPAD][512] fp16
__device__ __align__(16) float  g_amp[NMAX];
__device__ __align__(16) float  g_att[NMAX];
__device__ __align__(16) __half g_Wh_uv[256*128];               // [n=256][k=128] fp16
__device__ __align__(16) float  g_Wt_lin[FDIM*FDIM];            // [128][128] (k-major)
__device__ __align__(16) __half g_Wh_comb[(size_t)FDIM*KPOST];  // [n=128][k=1664] fp16
__device__ __align__(16) float  g_b_comb[FDIM];

__device__ __forceinline__ uint32_t s2u(const void* p){
    return (uint32_t)__cvta_generic_to_shared(p);
}
__device__ __forceinline__ void cp_async16(uint32_t smem, const void* gmem){
    asm volatile("cp.async.cg.shared.global [%0], [%1], 16;\n" :: "r"(smem), "l"(gmem));
}
#define CP_COMMIT() asm volatile("cp.async.commit_group;\n" ::: "memory")
#define CP_WAIT0()  asm volatile("cp.async.wait_group 0;\n" ::: "memory")
#define CP_WAIT1()  asm volatile("cp.async.wait_group 1;\n" ::: "memory")

#define MMA_F16(acc, a0,a1,a2,a3, b0,b1) \
    asm volatile( \
        "mma.sync.aligned.m16n8k16.row.col.f32.f16.f16.f32 " \
        "{%0,%1,%2,%3}, {%4,%5,%6,%7}, {%8,%9}, {%0,%1,%2,%3};\n" \
        : "+f"((acc)[0]), "+f"((acc)[1]), "+f"((acc)[2]), "+f"((acc)[3]) \
        : "r"(a0), "r"(a1), "r"(a2), "r"(a3), "r"(b0), "r"(b1))

#define PITCH 40   /* halves per smem row: (row*20+qid)%32 covers all banks */

// ---------------- CSR build --------------------------------------------------
__global__ void k_zero(int n){
    int i = blockIdx.x*blockDim.x + threadIdx.x;
    if (i < n) g_deg[i] = 0;
}

__global__ void k_hist(const int* __restrict__ dst, int E){
    int e = blockIdx.x*blockDim.x + threadIdx.x;
    if (e < E) atomicAdd(&g_deg[dst[e]], 1);
}

__global__ void k_scan(int n){
    __shared__ int ss[1024];
    int t = threadIdx.x;
    int chunk = (n + 1023) >> 10;
    int lo = t*chunk;
    int hi = min(lo + chunk, n);
    int s = 0;
    for (int i = lo; i < hi; i++) s += g_deg[i];
    ss[t] = s;
    __syncthreads();
    for (int off = 1; off < 1024; off <<= 1){
        int v = (t >= off) ? ss[t-off] : 0;
        __syncthreads();
        ss[t] += v;
        __syncthreads();
    }
    int run = (t == 0) ? 0 : ss[t-1];
    for (int i = lo; i < hi; i++){
        g_rowptr[i] = run;
        g_cursor[i] = run;
        run += g_deg[i];
    }
    if (t == 1023) g_rowptr[n] = ss[1023];
}

__global__ void k_scatter(const int* __restrict__ src, const int* __restrict__ dst, int E){
    int e = blockIdx.x*blockDim.x + threadIdx.x;
    if (e < E){
        int d = dst[e];
        int p = atomicAdd(&g_cursor[d], 1);
        g_srcs[p] = src[e];
    }
}

// ---------------- prep: fp16 conversions -------------------------------------
__global__ void k_xh(const float* __restrict__ x, int total){
    int i = blockIdx.x*256 + threadIdx.x;
    if (i < total) g_xh[i] = __float2half_rn(x[i]);
}

// g_Wh_uv[n=j][k] : j<128 -> W_pre[j][k] (u cols), j>=128 -> W_pre[j-128][128+k] (v)
__global__ void k_prep_uv(const float* __restrict__ W_pre){
    int idx = blockIdx.x*256 + threadIdx.x;
    if (idx < 256*128){
        int j = idx >> 7, k = idx & 127;
        float val = W_pre[(size_t)(j & 127)*256 + ((j >> 7) ? (128 + k) : k)];
        g_Wh_uv[idx] = __float2half_rn(val);
    }
}

__global__ void k_transpose_lin(const float* __restrict__ in){
    int idx = blockIdx.x*256 + threadIdx.x;
    if (idx < FDIM*FDIM){
        int f = idx >> 7, c = idx & 127;
        g_Wt_lin[c*FDIM + f] = in[idx];
    }
}

// g_Wh_comb[n=f][k=c] = fp16( sum_j W_lin[f][j] * W_post[j][c] )
__global__ void k_combine(const float* __restrict__ W_post){
    int c = blockIdx.x;
    int f = threadIdx.x;
    __shared__ float col[FDIM];
    col[f] = W_post[(size_t)f*KPOST + c];
    __syncthreads();
    float s = 0.f;
    #pragma unroll 8
    for (int k = 0; k < FDIM; k++)
        s = fmaf(g_Wt_lin[k*FDIM + f], col[k], s);
    g_Wh_comb[(size_t)f*KPOST + c] = __float2half_rn(s);
}

__global__ void k_bias(const float* __restrict__ b_post, const float* __restrict__ b_lin){
    int f = threadIdx.x;
    float s = b_lin[f];
    #pragma unroll 8
    for (int k = 0; k < FDIM; k++)
        s = fmaf(g_Wt_lin[k*FDIM + f], b_post[k], s);
    g_b_comb[f] = s;
}

// ---------------- u/v FP16 GEMM, cp.async double-buffered (K=128) ------------
// gridDim.y: 0 -> u (bias b_pre), 1 -> v (no bias)
__global__ void __launch_bounds__(256, 2)
k_uv_f16(int M, const float* __restrict__ b_pre)
{
    __shared__ __half As[2][128*PITCH];
    __shared__ __half Ws[2][128*PITCH];

    int tid  = threadIdx.x;
    int m0   = blockIdx.x * 128;
    int half_ = blockIdx.y;
    float* Cout = half_ ? g_v : g_u;
    int wid  = tid >> 5, lane = tid & 31;
    int wm   = (wid >> 1) * 32;
    int wn   = (wid & 1) * 64;
    int grp  = lane >> 2, qid = lane & 3;

    float acc[2][8][4];
    #pragma unroll
    for (int mt = 0; mt < 2; mt++)
        #pragma unroll
        for (int nt = 0; nt < 8; nt++)
            #pragma unroll
            for (int q = 0; q < 4; q++) acc[mt][nt][q] = 0.f;

    auto loadTile = [&](int t, int buf){
        // A: 128 rows x 32 halves (64B = 4x16B); 512 chunks
        #pragma unroll
        for (int i = 0; i < 2; i++){
            int idx = tid*2 + i;          // 0..511
            int rl  = idx >> 2, c4 = idx & 3;
            cp_async16(s2u(&As[buf][rl*PITCH + c4*8]),
                       g_xh + (size_t)(m0+rl)*128 + t*32 + c4*8);
        }
        #pragma unroll
        for (int i = 0; i < 2; i++){
            int idx = tid*2 + i;
            int nl  = idx >> 2, c4 = idx & 3;
            cp_async16(s2u(&Ws[buf][nl*PITCH + c4*8]),
                       g_Wh_uv + (size_t)(half_*128 + nl)*128 + t*32 + c4*8);
        }
    };

    const int T = 4;
    loadTile(0, 0); CP_COMMIT();
    loadTile(1, 1); CP_COMMIT();
    CP_WAIT1();
    __syncthreads();

    for (int t = 0; t < T; t++){
        int cur = t & 1;
        const __half* A = As[cur];
        const __half* W = Ws[cur];
        #pragma unroll
        for (int ks = 0; ks < 2; ks++){
            int kk = ks*16;
            uint32_t a[2][4], b[8][2];
            #pragma unroll
            for (int mt = 0; mt < 2; mt++){
                int row = wm + mt*16 + grp;
                a[mt][0] = *(const uint32_t*)&A[row*PITCH     + kk + 2*qid];
                a[mt][1] = *(const uint32_t*)&A[(row+8)*PITCH + kk + 2*qid];
                a[mt][2] = *(const uint32_t*)&A[row*PITCH     + kk + 8 + 2*qid];
                a[mt][3] = *(const uint32_t*)&A[(row+8)*PITCH + kk + 8 + 2*qid];
            }
            #pragma unroll
            for (int nt = 0; nt < 8; nt++){
                int col = wn + nt*8 + grp;
                b[nt][0] = *(const uint32_t*)&W[col*PITCH + kk + 2*qid];
                b[nt][1] = *(const uint32_t*)&W[col*PITCH + kk + 8 + 2*qid];
            }
            #pragma unroll
            for (int mt = 0; mt < 2; mt++)
                #pragma unroll
                for (int nt = 0; nt < 8; nt++)
                    MMA_F16(acc[mt][nt], a[mt][0],a[mt][1],a[mt][2],a[mt][3],
                            b[nt][0], b[nt][1]);
        }
        __syncthreads();
        if (t + 2 < T){
            loadTile(t + 2, cur); CP_COMMIT();
            CP_WAIT1();
            __syncthreads();
        } else if (t + 1 < T){
            CP_WAIT0();
            __syncthreads();
        }
    }

    #pragma unroll
    for (int mt = 0; mt < 2; mt++){
        int row0 = m0 + wm + mt*16 + grp;
        #pragma unroll
        for (int nt = 0; nt < 8; nt++){
            int col = wn + nt*8 + 2*qid;
            float b0 = half_ ? 0.f : b_pre[col];
            float b1 = half_ ? 0.f : b_pre[col+1];
            if (row0 < M){
                float2 v = make_float2(acc[mt][nt][0] + b0, acc[mt][nt][1] + b1);
                *(float2*)(Cout + (size_t)row0*128 + col) = v;
            }
            if (row0 + 8 < M){
                float2 v = make_float2(acc[mt][nt][2] + b0, acc[mt][nt][3] + b1);
                *(float2*)(Cout + (size_t)(row0+8)*128 + col) = v;
            }
        }
    }
}

// ---------------- per-node aggregation over CSR (fp16 out) -------------------
__global__ void k_agg(int n){
    int node = blockIdx.x;
    int f = threadIdx.x;
    int s0 = g_rowptr[node], s1 = g_rowptr[node+1];
    float uf = g_u[(size_t)node*FDIM + f];
    float mx = -3.402823466e38f, mn = 3.402823466e38f, sm = 0.f, sq = 0.f;
    int e = s0;
    for (; e + 3 < s1; e += 4){
        int i0 = g_srcs[e], i1 = g_srcs[e+1], i2 = g_srcs[e+2], i3 = g_srcs[e+3];
        float v0 = g_v[(size_t)i0*FDIM + f];
        float v1 = g_v[(size_t)i1*FDIM + f];
        float v2 = g_v[(size_t)i2*FDIM + f];
        float v3 = g_v[(size_t)i3*FDIM + f];
        float a0 = uf + v0, a1 = uf + v1, a2 = uf + v2, a3 = uf + v3;
        mx = fmaxf(mx, fmaxf(fmaxf(a0, a1), fmaxf(a2, a3)));
        mn = fminf(mn, fminf(fminf(a0, a1), fminf(a2, a3)));
        sm += a0 + a1 + a2 + a3;
        sq = fmaf(a0, a0, sq); sq = fmaf(a1, a1, sq);
        sq = fmaf(a2, a2, sq); sq = fmaf(a3, a3, sq);
    }
    for (; e < s1; e++){
        int s = g_srcs[e];
        float val = uf + g_v[(size_t)s*FDIM + f];
        mx = fmaxf(mx, val);
        mn = fminf(mn, val);
        sm += val;
        sq = fmaf(val, val, sq);
    }
    int deg = s1 - s0;
    if (deg == 0){ mx = 0.f; mn = 0.f; }
    float dc   = fmaxf((float)deg, 1.f);
    float mean = sm / dc;
    float var  = sq / dc - mean*mean;
    float sd   = sqrtf(fmaxf(var, 0.f) + 1e-5f);
    size_t b = (size_t)node * (4*FDIM);
    g_aggh[b + f]          = __float2half_rn(mx);
    g_aggh[b + FDIM + f]   = __float2half_rn(mn);
    g_aggh[b + 2*FDIM + f] = __float2half_rn(mean);
    g_aggh[b + 3*FDIM + f] = __float2half_rn(sd);
    if (f == 0){
        float ld = logf(dc + 1.f);   // DELTA = 1.0
        g_amp[node] = ld;
        g_att[node] = 1.f / ld;
    }
}

// ---------------- factored FP16 post GEMM ------------------------------------
// out = x@W0 + agg@W1 + amp.*(agg@W2) + att.*(agg@W3) + b_comb
#define P_TILE (128*PITCH)                 /* halves per A or W slot */
#define P_STAGE (4*P_TILE)                 /* A + 3 W slots          */
#define POST_SMEM_BYTES (2*P_STAGE*2)      /* 2 stages, fp16         */

__global__ void __launch_bounds__(256, 1)
k_post3(int M, float* __restrict__ C)
{
    extern __shared__ __half smh[];

    int tid  = threadIdx.x;
    int m0   = blockIdx.x * 128;
    int wid  = tid >> 5, lane = tid & 31;
    int wm   = (wid >> 1) * 32;
    int wn   = (wid & 1) * 64;
    int grp  = lane >> 2, qid = lane & 3;

    float accC[2][8][4], accA[2][8][4], accT[2][8][4];
    #pragma unroll
    for (int mt = 0; mt < 2; mt++)
        #pragma unroll
        for (int nt = 0; nt < 8; nt++)
            #pragma unroll
            for (int q = 0; q < 4; q++){
                accC[mt][nt][q] = 0.f; accA[mt][nt][q] = 0.f; accT[mt][nt][q] = 0.f;
            }

    auto loadTile = [&](int t, int buf){
        __half* S = smh + buf*P_STAGE;
        if (t < 4){
            int kc = t*32;
            #pragma unroll
            for (int i = 0; i < 2; i++){
                int idx = tid*2 + i;
                int rl  = idx >> 2, c4 = idx & 3;
                cp_async16(s2u(&S[rl*PITCH + c4*8]),
                           g_xh + (size_t)(m0+rl)*128 + kc + c4*8);
            }
            __half* W = S + P_TILE;
            #pragma unroll
            for (int i = 0; i < 2; i++){
                int idx = tid*2 + i;
                int nl  = idx >> 2, c4 = idx & 3;
                cp_async16(s2u(&W[nl*PITCH + c4*8]),
                           g_Wh_comb + (size_t)nl*KPOST + kc + c4*8);
            }
        } else {
            int ka = (t-4)*32;
            #pragma unroll
            for (int i = 0; i < 2; i++){
                int idx = tid*2 + i;
                int rl  = idx >> 2, c4 = idx & 3;
                cp_async16(s2u(&S[rl*PITCH + c4*8]),
                           g_aggh + (size_t)(m0+rl)*512 + ka + c4*8);
            }
            const int OFF[3] = { 128, 640, 1152 };
            #pragma unroll
            for (int j = 0; j < 3; j++){
                __half* W = S + P_TILE + j*P_TILE;
                #pragma unroll
                for (int i = 0; i < 2; i++){
                    int idx = tid*2 + i;
                    int nl  = idx >> 2, c4 = idx & 3;
                    cp_async16(s2u(&W[nl*PITCH + c4*8]),
                               g_Wh_comb + (size_t)nl*KPOST + OFF[j] + ka + c4*8);
                }
            }
        }
    };

    const int T = 20;
    loadTile(0, 0); CP_COMMIT();
    loadTile(1, 1); CP_COMMIT();
    CP_WAIT1();
    __syncthreads();

    for (int t = 0; t < T; t++){
        int cur = t & 1;
        const __half* S = smh + cur*P_STAGE;
        int nsets = (t < 4) ? 1 : 3;
        #pragma unroll
        for (int ks = 0; ks < 2; ks++){
            int kk = ks*16;
            uint32_t a[2][4];
            #pragma unroll
            for (int mt = 0; mt < 2; mt++){
                int row = wm + mt*16 + grp;
                a[mt][0] = *(const uint32_t*)&S[row*PITCH     + kk + 2*qid];
                a[mt][1] = *(const uint32_t*)&S[(row+8)*PITCH + kk + 2*qid];
                a[mt][2] = *(const uint32_t*)&S[row*PITCH     + kk + 8 + 2*qid];
                a[mt][3] = *(const uint32_t*)&S[(row+8)*PITCH + kk + 8 + 2*qid];
            }
            #pragma unroll
            for (int s = 0; s < 3; s++){
                if (s >= nsets) break;
                const __half* W = S + P_TILE + s*P_TILE;
                uint32_t b[8][2];
                #pragma unroll
                for (int nt = 0; nt < 8; nt++){
                    int col = wn + nt*8 + grp;
                    b[nt][0] = *(const uint32_t*)&W[col*PITCH + kk + 2*qid];
                    b[nt][1] = *(const uint32_t*)&W[col*PITCH + kk + 8 + 2*qid];
                }
                float (*acc)[8][4] = (s == 0) ? accC : (s == 1) ? accA : accT;
                #pragma unroll
                for (int mt = 0; mt < 2; mt++)
                    #pragma unroll
                    for (int nt = 0; nt < 8; nt++)
                        MMA_F16(acc[mt][nt], a[mt][0],a[mt][1],a[mt][2],a[mt][3],
                                b[nt][0], b[nt][1]);
            }
        }
        __syncthreads();
        if (t + 2 < T){
            loadTile(t + 2, cur); CP_COMMIT();
            CP_WAIT1();
            __syncthreads();
        } else if (t + 1 < T){
            CP_WAIT0();
            __syncthreads();
        }
    }

    #pragma unroll
    for (int mt = 0; mt < 2; mt++){
        int row0 = m0 + wm + mt*16 + grp;
        int row1 = row0 + 8;
        float amp0 = 0.f, att0 = 0.f, amp1 = 0.f, att1 = 0.f;
        if (row0 < M){ amp0 = g_amp[row0]; att0 = g_att[row0]; }
        if (row1 < M){ amp1 = g_amp[row1]; att1 = g_att[row1]; }
        #pragma unroll
        for (int nt = 0; nt < 8; nt++){
            int col = wn + nt*8 + 2*qid;
            float b0 = g_b_comb[col], b1 = g_b_comb[col+1];
            if (row0 < M){
                float2 v;
                v.x = accC[mt][nt][0] + amp0*accA[mt][nt][0] + att0*accT[mt][nt][0] + b0;
                v.y = accC[mt][nt][1] + amp0*accA[mt][nt][1] + att0*accT[mt][nt][1] + b1;
                *(float2*)(C + (size_t)row0*128 + col) = v;
            }
            if (row1 < M){
                float2 v;
                v.x = accC[mt][nt][2] + amp1*accA[mt][nt][2] + att1*accT[mt][nt][2] + b0;
                v.y = accC[mt][nt][3] + amp1*accA[mt][nt][3] + att1*accT[mt][nt][3] + b1;
                *(float2*)(C + (size_t)row1*128 + col) = v;
            }
        }
    }
}

// ---------------- launch -----------------------------------------------------
extern "C" void kernel_launch(void* const* d_in, const int* in_sizes, int n_in,
                              void* d_out, int out_size)
{
    const float* x      = (const float*)d_in[0];
    const int*   ei     = (const int*)  d_in[1];
    const float* W_pre  = (const float*)d_in[2];
    const float* b_pre  = (const float*)d_in[3];
    const float* W_post = (const float*)d_in[4];
    const float* b_post = (const float*)d_in[5];
    const float* W_lin  = (const float*)d_in[6];
    const float* b_lin  = (const float*)d_in[7];
    float* out = (float*)d_out;

    int N = in_sizes[0] / FDIM;
    int E = in_sizes[1] / 2;
    const int* src = ei;        // edge_index[0] = x_j (source)
    const int* dst = ei + E;    // edge_index[1] = x_i (destination)

    cudaFuncSetAttribute(k_post3,
                         cudaFuncAttributeMaxDynamicSharedMemorySize, POST_SMEM_BYTES);

    // CSR build
    k_zero   <<<(N+255)/256, 256>>>(N);
    k_hist   <<<(E+255)/256, 256>>>(dst, E);
    k_scan   <<<1, 1024>>>(N);
    k_scatter<<<(E+255)/256, 256>>>(src, dst, E);

    // prep: fp16 conversions + combined weights
    k_xh<<<(N*FDIM+255)/256, 256>>>(x, N*FDIM);
    k_prep_uv<<<128, 256>>>(W_pre);
    k_transpose_lin<<<64, 256>>>(W_lin);
    k_combine<<<KPOST, FDIM>>>(W_post);
    k_bias<<<1, FDIM>>>(b_post, b_lin);

    // u/v fp16 GEMM (pipelined)
    int gm = (N + 127) / 128;
    dim3 guv(gm, 2);
    k_uv_f16<<<guv, 256>>>(N, b_pre);

    // aggregation (fp16 agg out + amp/att)
    k_agg<<<N, FDIM>>>(N);

    // factored fp16 post GEMM (3 accumulator sets)
    k_post3<<<gm, 256, POST_SMEM_BYTES>>>(N, out);
}

// round 10
// speedup vs baseline: 3.5584x; 1.1366x over previous
#include <cuda_runtime.h>
#include <cuda_fp16.h>
#include <math.h>
#include <stdint.h>

#define FDIM 128
#define NMAX 50000
#define NPAD (NMAX + 128)
#define EMAX 800000
#define KPOST (13*FDIM)   /* 1664 */

// ---------------- scratch (static device globals; no allocation) -------------
__device__ __align__(16) int    g_deg[NMAX];
__device__ __align__(16) int    g_rowptr[NMAX+1];
__device__ __align__(16) int    g_cursor[NMAX];
__device__ __align__(16) int    g_srcs[EMAX];
__device__ __align__(16) float  g_u[(size_t)NMAX*FDIM];
__device__ __align__(16) __half g_vh[(size_t)NMAX*FDIM];        // fp16 v
__device__ __align__(16) __half g_xh[(size_t)NPAD*FDIM];        // fp16 x
__device__ __align__(16) __half g_aggh[(size_t)NPAD*4*FDIM];    // [NPAD][512] fp16
__device__ __align__(16) float  g_amp[NMAX];
__device__ __align__(16) float  g_att[NMAX];
__device__ __align__(16) __half g_Wh_uv[256*128];               // [n=256][k=128] fp16
__device__ __align__(16) float  g_Wt_lin[FDIM*FDIM];            // [128][128] (k-major)
__device__ __align__(16) __half g_Wh_comb[(size_t)FDIM*KPOST];  // [n=128][k=1664] fp16
__device__ __align__(16) float  g_b_comb[FDIM];

__device__ __forceinline__ uint32_t s2u(const void* p){
    return (uint32_t)__cvta_generic_to_shared(p);
}
__device__ __forceinline__ void cp_async16(uint32_t smem, const void* gmem){
    asm volatile("cp.async.cg.shared.global [%0], [%1], 16;\n" :: "r"(smem), "l"(gmem));
}
#define CP_COMMIT() asm volatile("cp.async.commit_group;\n" ::: "memory")
#define CP_WAIT0()  asm volatile("cp.async.wait_group 0;\n" ::: "memory")
#define CP_WAIT1()  asm volatile("cp.async.wait_group 1;\n" ::: "memory")

#define MMA_F16(acc, a0,a1,a2,a3, b0,b1) \
    asm volatile( \
        "mma.sync.aligned.m16n8k16.row.col.f32.f16.f16.f32 " \
        "{%0,%1,%2,%3}, {%4,%5,%6,%7}, {%8,%9}, {%0,%1,%2,%3};\n" \
        : "+f"((acc)[0]), "+f"((acc)[1]), "+f"((acc)[2]), "+f"((acc)[3]) \
        : "r"(a0), "r"(a1), "r"(a2), "r"(a3), "r"(b0), "r"(b1))

#define LDSM_X4(r0,r1,r2,r3,addr) \
    asm volatile("ldmatrix.sync.aligned.m8n8.x4.shared.b16 {%0,%1,%2,%3}, [%4];" \
        : "=r"(r0), "=r"(r1), "=r"(r2), "=r"(r3) : "r"(addr))

#define PITCH 40   /* halves per smem row: rows hit all-distinct banks */

// ---------------- CSR build --------------------------------------------------
__global__ void k_zero(int n){
    int i = blockIdx.x*blockDim.x + threadIdx.x;
    if (i < n) g_deg[i] = 0;
}

__global__ void k_hist(const int* __restrict__ dst, int E){
    int e = blockIdx.x*blockDim.x + threadIdx.x;
    if (e < E) atomicAdd(&g_deg[dst[e]], 1);
}

__global__ void k_scan(int n){
    __shared__ int ss[1024];
    int t = threadIdx.x;
    int chunk = (n + 1023) >> 10;
    int lo = t*chunk;
    int hi = min(lo + chunk, n);
    int s = 0;
    for (int i = lo; i < hi; i++) s += g_deg[i];
    ss[t] = s;
    __syncthreads();
    for (int off = 1; off < 1024; off <<= 1){
        int v = (t >= off) ? ss[t-off] : 0;
        __syncthreads();
        ss[t] += v;
        __syncthreads();
    }
    int run = (t == 0) ? 0 : ss[t-1];
    for (int i = lo; i < hi; i++){
        g_rowptr[i] = run;
        g_cursor[i] = run;
        run += g_deg[i];
    }
    if (t == 1023) g_rowptr[n] = ss[1023];
}

__global__ void k_scatter(const int* __restrict__ src, const int* __restrict__ dst, int E){
    int e = blockIdx.x*blockDim.x + threadIdx.x;
    if (e < E){
        int d = dst[e];
        int p = atomicAdd(&g_cursor[d], 1);
        g_srcs[p] = src[e];
    }
}

// ---------------- merged prep: xh + Wuv + lin-transpose ----------------------
__global__ void k_prep(const float* __restrict__ x, const float* __restrict__ W_pre,
                       const float* __restrict__ W_lin, int N){
    int stride = gridDim.x*blockDim.x;
    int i0 = blockIdx.x*blockDim.x + threadIdx.x;
    for (int i = i0; i < N*FDIM; i += stride)
        g_xh[i] = __float2half_rn(x[i]);
    for (int i = i0; i < 256*128; i += stride){
        int j = i >> 7, k = i & 127;
        g_Wh_uv[i] = __float2half_rn(W_pre[(size_t)(j & 127)*256 + ((j >> 7) ? (128 + k) : k)]);
    }
    for (int i = i0; i < FDIM*FDIM; i += stride){
        int f = i >> 7, c = i & 127;
        g_Wt_lin[c*FDIM + f] = W_lin[i];
    }
}

// g_Wh_comb[n=f][k=c] = fp16( sum_j W_lin[f][j] * W_post[j][c] ); block KPOST = bias
__global__ void k_combine(const float* __restrict__ W_post,
                          const float* __restrict__ b_post,
                          const float* __restrict__ b_lin){
    int f = threadIdx.x;
    if (blockIdx.x == KPOST){
        float s = b_lin[f];
        #pragma unroll 8
        for (int k = 0; k < FDIM; k++)
            s = fmaf(g_Wt_lin[k*FDIM + f], b_post[k], s);
        g_b_comb[f] = s;
        return;
    }
    int c = blockIdx.x;
    __shared__ float col[FDIM];
    col[f] = W_post[(size_t)f*KPOST + c];
    __syncthreads();
    float s = 0.f;
    #pragma unroll 8
    for (int k = 0; k < FDIM; k++)
        s = fmaf(g_Wt_lin[k*FDIM + f], col[k], s);
    g_Wh_comb[(size_t)f*KPOST + c] = __float2half_rn(s);
}

// ---------------- u/v FP16 GEMM, ldmatrix + cp.async (K=128) -----------------
// gridDim.y: 0 -> u (fp32 + bias), 1 -> v (fp16, no bias)
__global__ void __launch_bounds__(256, 2)
k_uv_f16(int M, const float* __restrict__ b_pre)
{
    __shared__ __half As[2][128*PITCH];
    __shared__ __half Ws[2][128*PITCH];

    int tid  = threadIdx.x;
    int m0   = blockIdx.x * 128;
    int half_ = blockIdx.y;
    int wid  = tid >> 5, lane = tid & 31;
    int wm   = (wid >> 1) * 32;
    int wn   = (wid & 1) * 64;
    int grp  = lane >> 2, qid = lane & 3;

    // ldmatrix lane mappings
    int arow  = (lane & 7) + ((lane >> 3) & 1) * 8;
    int aksel = (lane >> 4) * 8;
    int brow  = (lane & 7) + ((lane >> 4) ? 8 : 0);
    int bksel = ((lane >> 3) & 1) * 8;

    float acc[2][8][4];
    #pragma unroll
    for (int mt = 0; mt < 2; mt++)
        #pragma unroll
        for (int nt = 0; nt < 8; nt++)
            #pragma unroll
            for (int q = 0; q < 4; q++) acc[mt][nt][q] = 0.f;

    auto loadTile = [&](int t, int buf){
        #pragma unroll
        for (int i = 0; i < 2; i++){
            int idx = tid*2 + i;
            int rl  = idx >> 2, c4 = idx & 3;
            cp_async16(s2u(&As[buf][rl*PITCH + c4*8]),
                       g_xh + (size_t)(m0+rl)*128 + t*32 + c4*8);
        }
        #pragma unroll
        for (int i = 0; i < 2; i++){
            int idx = tid*2 + i;
            int nl  = idx >> 2, c4 = idx & 3;
            cp_async16(s2u(&Ws[buf][nl*PITCH + c4*8]),
                       g_Wh_uv + (size_t)(half_*128 + nl)*128 + t*32 + c4*8);
        }
    };

    const int T = 4;
    loadTile(0, 0); CP_COMMIT();
    loadTile(1, 1); CP_COMMIT();
    CP_WAIT1();
    __syncthreads();

    for (int t = 0; t < T; t++){
        int cur = t & 1;
        const __half* A = As[cur];
        const __half* W = Ws[cur];
        #pragma unroll
        for (int ks = 0; ks < 2; ks++){
            int kk = ks*16;
            uint32_t a[2][4], b[8][2];
            #pragma unroll
            for (int mt = 0; mt < 2; mt++){
                uint32_t addr = s2u(&A[(wm + mt*16 + arow)*PITCH + kk + aksel]);
                LDSM_X4(a[mt][0], a[mt][1], a[mt][2], a[mt][3], addr);
            }
            #pragma unroll
            for (int p = 0; p < 4; p++){
                uint32_t addr = s2u(&W[(wn + p*16 + brow)*PITCH + kk + bksel]);
                LDSM_X4(b[2*p][0], b[2*p][1], b[2*p+1][0], b[2*p+1][1], addr);
            }
            #pragma unroll
            for (int mt = 0; mt < 2; mt++)
                #pragma unroll
                for (int nt = 0; nt < 8; nt++)
                    MMA_F16(acc[mt][nt], a[mt][0],a[mt][1],a[mt][2],a[mt][3],
                            b[nt][0], b[nt][1]);
        }
        __syncthreads();
        if (t + 2 < T){
            loadTile(t + 2, cur); CP_COMMIT();
            CP_WAIT1();
            __syncthreads();
        } else if (t + 1 < T){
            CP_WAIT0();
            __syncthreads();
        }
    }

    #pragma unroll
    for (int mt = 0; mt < 2; mt++){
        int row0 = m0 + wm + mt*16 + grp;
        #pragma unroll
        for (int nt = 0; nt < 8; nt++){
            int col = wn + nt*8 + 2*qid;
            if (half_){
                if (row0 < M)
                    *(__half2*)(g_vh + (size_t)row0*128 + col) =
                        __floats2half2_rn(acc[mt][nt][0], acc[mt][nt][1]);
                if (row0 + 8 < M)
                    *(__half2*)(g_vh + (size_t)(row0+8)*128 + col) =
                        __floats2half2_rn(acc[mt][nt][2], acc[mt][nt][3]);
            } else {
                float b0 = b_pre[col], b1 = b_pre[col+1];
                if (row0 < M)
                    *(float2*)(g_u + (size_t)row0*128 + col) =
                        make_float2(acc[mt][nt][0] + b0, acc[mt][nt][1] + b1);
                if (row0 + 8 < M)
                    *(float2*)(g_u + (size_t)(row0+8)*128 + col) =
                        make_float2(acc[mt][nt][2] + b0, acc[mt][nt][3] + b1);
            }
        }
    }
}

// ---------------- per-node aggregation (factored u, fp16 v gathers) ----------
// 2 nodes / 128-thread block; 64 threads/node; half2 = 2 features/thread
__global__ void k_agg(int n){
    int node = blockIdx.x*2 + (threadIdx.x >> 6);
    int t = threadIdx.x & 63;
    if (node >= n) return;
    int s0 = g_rowptr[node], s1 = g_rowptr[node+1];
    const __half2* vh = (const __half2*)g_vh;

    __half2 hmx = __half2half2(__ushort_as_half((unsigned short)0xFC00));  // -inf
    __half2 hmn = __half2half2(__ushort_as_half((unsigned short)0x7C00));  // +inf
    float smx = 0.f, smy = 0.f, sqx = 0.f, sqy = 0.f;

    int e = s0;
    for (; e + 3 < s1; e += 4){
        int i0 = g_srcs[e], i1 = g_srcs[e+1], i2 = g_srcs[e+2], i3 = g_srcs[e+3];
        __half2 v0 = vh[(size_t)i0*64 + t];
        __half2 v1 = vh[(size_t)i1*64 + t];
        __half2 v2 = vh[(size_t)i2*64 + t];
        __half2 v3 = vh[(size_t)i3*64 + t];
        hmx = __hmax2(hmx, __hmax2(__hmax2(v0, v1), __hmax2(v2, v3)));
        hmn = __hmin2(hmn, __hmin2(__hmin2(v0, v1), __hmin2(v2, v3)));
        float2 f0 = __half22float2(v0), f1 = __half22float2(v1);
        float2 f2 = __half22float2(v2), f3 = __half22float2(v3);
        smx += f0.x + f1.x + f2.x + f3.x;
        smy += f0.y + f1.y + f2.y + f3.y;
        sqx = fmaf(f0.x, f0.x, sqx); sqx = fmaf(f1.x, f1.x, sqx);
        sqx = fmaf(f2.x, f2.x, sqx); sqx = fmaf(f3.x, f3.x, sqx);
        sqy = fmaf(f0.y, f0.y, sqy); sqy = fmaf(f1.y, f1.y, sqy);
        sqy = fmaf(f2.y, f2.y, sqy); sqy = fmaf(f3.y, f3.y, sqy);
    }
    for (; e < s1; e++){
        int s = g_srcs[e];
        __half2 v = vh[(size_t)s*64 + t];
        hmx = __hmax2(hmx, v);
        hmn = __hmin2(hmn, v);
        float2 f = __half22float2(v);
        smx += f.x; smy += f.y;
        sqx = fmaf(f.x, f.x, sqx);
        sqy = fmaf(f.y, f.y, sqy);
    }

    int deg = s1 - s0;
    float dc = fmaxf((float)deg, 1.f);
    float inv = 1.f / dc;
    float2 uf = *(const float2*)(g_u + (size_t)node*128 + 2*t);

    float vmx_x = __half2float(__low2half(hmx)),  vmx_y = __half2float(__high2half(hmx));
    float vmn_x = __half2float(__low2half(hmn)),  vmn_y = __half2float(__high2half(hmn));
    float vme_x = smx*inv, vme_y = smy*inv;

    float mxx = deg ? (uf.x + vmx_x) : 0.f;
    float mxy = deg ? (uf.y + vmx_y) : 0.f;
    float mnx = deg ? (uf.x + vmn_x) : 0.f;
    float mny = deg ? (uf.y + vmn_y) : 0.f;
    float mex = deg ? (uf.x + vme_x) : 0.f;
    float mey = deg ? (uf.y + vme_y) : 0.f;
    float sdx = sqrtf(fmaxf(sqx*inv - vme_x*vme_x, 0.f) + 1e-5f);
    float sdy = sqrtf(fmaxf(sqy*inv - vme_y*vme_y, 0.f) + 1e-5f);

    __half2* ag = (__half2*)(g_aggh + (size_t)node*512);
    ag[t]       = __floats2half2_rn(mxx, mxy);
    ag[64 + t]  = __floats2half2_rn(mnx, mny);
    ag[128 + t] = __floats2half2_rn(mex, mey);
    ag[192 + t] = __floats2half2_rn(sdx, sdy);

    if (t == 0){
        float ld = logf(dc + 1.f);   // DELTA = 1.0
        g_amp[node] = ld;
        g_att[node] = 1.f / ld;
    }
}

// ---------------- factored FP16 post GEMM (ldmatrix) -------------------------
// out = x@W0 + agg@W1 + amp.*(agg@W2) + att.*(agg@W3) + b_comb
#define P_TILE (128*PITCH)
#define P_STAGE (4*P_TILE)
#define POST_SMEM_BYTES (2*P_STAGE*2)

__global__ void __launch_bounds__(256, 1)
k_post3(int M, float* __restrict__ C)
{
    extern __shared__ __half smh[];

    int tid  = threadIdx.x;
    int m0   = blockIdx.x * 128;
    int wid  = tid >> 5, lane = tid & 31;
    int wm   = (wid >> 1) * 32;
    int wn   = (wid & 1) * 64;
    int grp  = lane >> 2, qid = lane & 3;

    int arow  = (lane & 7) + ((lane >> 3) & 1) * 8;
    int aksel = (lane >> 4) * 8;
    int brow  = (lane & 7) + ((lane >> 4) ? 8 : 0);
    int bksel = ((lane >> 3) & 1) * 8;

    float accC[2][8][4], accA[2][8][4], accT[2][8][4];
    #pragma unroll
    for (int mt = 0; mt < 2; mt++)
        #pragma unroll
        for (int nt = 0; nt < 8; nt++)
            #pragma unroll
            for (int q = 0; q < 4; q++){
                accC[mt][nt][q] = 0.f; accA[mt][nt][q] = 0.f; accT[mt][nt][q] = 0.f;
            }

    auto loadTile = [&](int t, int buf){
        __half* S = smh + buf*P_STAGE;
        if (t < 4){
            int kc = t*32;
            #pragma unroll
            for (int i = 0; i < 2; i++){
                int idx = tid*2 + i;
                int rl  = idx >> 2, c4 = idx & 3;
                cp_async16(s2u(&S[rl*PITCH + c4*8]),
                           g_xh + (size_t)(m0+rl)*128 + kc + c4*8);
            }
            __half* W = S + P_TILE;
            #pragma unroll
            for (int i = 0; i < 2; i++){
                int idx = tid*2 + i;
                int nl  = idx >> 2, c4 = idx & 3;
                cp_async16(s2u(&W[nl*PITCH + c4*8]),
                           g_Wh_comb + (size_t)nl*KPOST + kc + c4*8);
            }
        } else {
            int ka = (t-4)*32;
            #pragma unroll
            for (int i = 0; i < 2; i++){
                int idx = tid*2 + i;
                int rl  = idx >> 2, c4 = idx & 3;
                cp_async16(s2u(&S[rl*PITCH + c4*8]),
                           g_aggh + (size_t)(m0+rl)*512 + ka + c4*8);
            }
            const int OFF[3] = { 128, 640, 1152 };
            #pragma unroll
            for (int j = 0; j < 3; j++){
                __half* W = S + P_TILE + j*P_TILE;
                #pragma unroll
                for (int i = 0; i < 2; i++){
                    int idx = tid*2 + i;
                    int nl  = idx >> 2, c4 = idx & 3;
                    cp_async16(s2u(&W[nl*PITCH + c4*8]),
                               g_Wh_comb + (size_t)nl*KPOST + OFF[j] + ka + c4*8);
                }
            }
        }
    };

    const int T = 20;
    loadTile(0, 0); CP_COMMIT();
    loadTile(1, 1); CP_COMMIT();
    CP_WAIT1();
    __syncthreads();

    for (int t = 0; t < T; t++){
        int cur = t & 1;
        const __half* S = smh + cur*P_STAGE;
        int nsets = (t < 4) ? 1 : 3;
        #pragma unroll
        for (int ks = 0; ks < 2; ks++){
            int kk = ks*16;
            uint32_t a[2][4];
            #pragma unroll
            for (int mt = 0; mt < 2; mt++){
                uint32_t addr = s2u(&S[(wm + mt*16 + arow)*PITCH + kk + aksel]);
                LDSM_X4(a[mt][0], a[mt][1], a[mt][2], a[mt][3], addr);
            }
            #pragma unroll
            for (int s = 0; s < 3; s++){
                if (s >= nsets) break;
                const __half* W = S + P_TILE + s*P_TILE;
                uint32_t b[8][2];
                #pragma unroll
                for (int p = 0; p < 4; p++){
                    uint32_t addr = s2u(&W[(wn + p*16 + brow)*PITCH + kk + bksel]);
                    LDSM_X4(b[2*p][0], b[2*p][1], b[2*p+1][0], b[2*p+1][1], addr);
                }
                float (*acc)[8][4] = (s == 0) ? accC : (s == 1) ? accA : accT;
                #pragma unroll
                for (int mt = 0; mt < 2; mt++)
                    #pragma unroll
                    for (int nt = 0; nt < 8; nt++)
                        MMA_F16(acc[mt][nt], a[mt][0],a[mt][1],a[mt][2],a[mt][3],
                                b[nt][0], b[nt][1]);
            }
        }
        __syncthreads();
        if (t + 2 < T){
            loadTile(t + 2, cur); CP_COMMIT();
            CP_WAIT1();
            __syncthreads();
        } else if (t + 1 < T){
            CP_WAIT0();
            __syncthreads();
        }
    }

    #pragma unroll
    for (int mt = 0; mt < 2; mt++){
        int row0 = m0 + wm + mt*16 + grp;
        int row1 = row0 + 8;
        float amp0 = 0.f, att0 = 0.f, amp1 = 0.f, att1 = 0.f;
        if (row0 < M){ amp0 = g_amp[row0]; att0 = g_att[row0]; }
        if (row1 < M){ amp1 = g_amp[row1]; att1 = g_att[row1]; }
        #pragma unroll
        for (int nt = 0; nt < 8; nt++){
            int col = wn + nt*8 + 2*qid;
            float b0 = g_b_comb[col], b1 = g_b_comb[col+1];
            if (row0 < M){
                float2 v;
                v.x = accC[mt][nt][0] + amp0*accA[mt][nt][0] + att0*accT[mt][nt][0] + b0;
                v.y = accC[mt][nt][1] + amp0*accA[mt][nt][1] + att0*accT[mt][nt][1] + b1;
                *(float2*)(C + (size_t)row0*128 + col) = v;
            }
            if (row1 < M){
                float2 v;
                v.x = accC[mt][nt][2] + amp1*accA[mt][nt][2] + att1*accT[mt][nt][2] + b0;
                v.y = accC[mt][nt][3] + amp1*accA[mt][nt][3] + att1*accT[mt][nt][3] + b1;
                *(float2*)(C + (size_t)row1*128 + col) = v;
            }
        }
    }
}

// ---------------- launch -----------------------------------------------------
extern "C" void kernel_launch(void* const* d_in, const int* in_sizes, int n_in,
                              void* d_out, int out_size)
{
    const float* x      = (const float*)d_in[0];
    const int*   ei     = (const int*)  d_in[1];
    const float* W_pre  = (const float*)d_in[2];
    const float* b_pre  = (const float*)d_in[3];
    const float* W_post = (const float*)d_in[4];
    const float* b_post = (const float*)d_in[5];
    const float* W_lin  = (const float*)d_in[6];
    const float* b_lin  = (const float*)d_in[7];
    float* out = (float*)d_out;

    int N = in_sizes[0] / FDIM;
    int E = in_sizes[1] / 2;
    const int* src = ei;        // edge_index[0] = x_j (source)
    const int* dst = ei + E;    // edge_index[1] = x_i (destination)

    cudaFuncSetAttribute(k_post3,
                         cudaFuncAttributeMaxDynamicSharedMemorySize, POST_SMEM_BYTES);

    // CSR build
    k_zero   <<<(N+255)/256, 256>>>(N);
    k_hist   <<<(E+255)/256, 256>>>(dst, E);
    k_scan   <<<1, 1024>>>(N);
    k_scatter<<<(E+255)/256, 256>>>(src, dst, E);

    // merged prep + combined weights
    k_prep<<<(N*FDIM+255)/256, 256>>>(x, W_pre, W_lin, N);
    k_combine<<<KPOST+1, FDIM>>>(W_post, b_post, b_lin);

    // u/v fp16 GEMM
    int gm = (N + 127) / 128;
    dim3 guv(gm, 2);
    k_uv_f16<<<guv, 256>>>(N, b_pre);

    // factored aggregation (fp16 gathers)
    k_agg<<<(N+1)/2, 128>>>(N);

    // factored fp16 post GEMM
    k_post3<<<gm, 256, POST_SMEM_BYTES>>>(N, out);
}

// round 11
// speedup vs baseline: 3.8799x; 1.0903x over previous
#include <cuda_runtime.h>
#include <cuda_fp16.h>
#include <math.h>
#include <stdint.h>

#define FDIM 128
#define NMAX 50000
#define EMAX 800000
#define KPOST (13*FDIM)   /* 1664 */
#define NT    ((NMAX + 127)/128)   /* 391 m-tiles */
#define PITCH 40                   /* halves per smem/blocked row */
#define BLKH  (128*PITCH)          /* halves per block: 5120 */
#define BLKB  (BLKH*2)             /* bytes per block: 10240 */

// ---------------- scratch (static device globals; no allocation) -------------
__device__ __align__(16) int    g_deg[NMAX];
__device__ __align__(16) int    g_rowptr[NMAX+1];
__device__ __align__(16) int    g_cursor[NMAX];
__device__ __align__(16) int    g_srcs[EMAX];
__device__ __align__(16) float  g_u[(size_t)NMAX*FDIM];
__device__ __align__(16) __half g_vh[(size_t)NMAX*FDIM];          // fp16 v (row-major)
__device__ __align__(16) __half g_xb[(size_t)NT*4*BLKH];          // x, chunk-blocked
__device__ __align__(16) __half g_aggb[(size_t)NT*16*BLKH];       // agg, chunk-blocked
__device__ __align__(16) float  g_amp[NMAX];
__device__ __align__(16) float  g_att[NMAX];
__device__ __align__(16) __half g_wuvb[2*4*BLKH];                 // W_uv, blocked
__device__ __align__(16) float  g_Wt_lin[FDIM*FDIM];              // [128][128] (k-major)
__device__ __align__(16) __half g_wcb[52*BLKH];                   // W_comb, blocked
__device__ __align__(16) float  g_b_comb[FDIM];

__device__ __forceinline__ uint32_t s2u(const void* p){
    return (uint32_t)__cvta_generic_to_shared(p);
}

// ---- cp.async.bulk (non-tensor, sm_90 baseline) + mbarrier ------------------
__device__ __forceinline__ void bulk_g2s(uint32_t dst, const void* src,
                                         uint32_t bytes, uint32_t mbar){
    uint64_t g;
    asm("cvta.to.global.u64 %0, %1;" : "=l"(g) : "l"(src));
    asm volatile(
        "cp.async.bulk.shared::cta.global.mbarrier::complete_tx::bytes "
        "[%0], [%1], %2, [%3];"
        :: "r"(dst), "l"(g), "r"(bytes), "r"(mbar) : "memory");
}
__device__ __forceinline__ void mbar_init(uint32_t mbar, uint32_t cnt){
    asm volatile("mbarrier.init.shared.b64 [%0], %1;" :: "r"(mbar), "r"(cnt) : "memory");
}
__device__ __forceinline__ void mbar_expect_tx(uint32_t mbar, uint32_t bytes){
    asm volatile("mbarrier.arrive.expect_tx.shared.b64 _, [%0], %1;"
                 :: "r"(mbar), "r"(bytes) : "memory");
}
__device__ __forceinline__ void mbar_wait(uint32_t mbar, uint32_t parity){
    uint32_t done = 0;
    while (!done){
        asm volatile(
            "{\n\t"
            ".reg .pred p;\n\t"
            "mbarrier.try_wait.parity.acquire.cta.shared::cta.b64 p, [%1], %2, 0x989680;\n\t"
            "selp.b32 %0, 1, 0, p;\n\t"
            "}"
            : "=r"(done) : "r"(mbar), "r"(parity) : "memory");
    }
}

#define MMA_F16(acc, a0,a1,a2,a3, b0,b1) \
    asm volatile( \
        "mma.sync.aligned.m16n8k16.row.col.f32.f16.f16.f32 " \
        "{%0,%1,%2,%3}, {%4,%5,%6,%7}, {%8,%9}, {%0,%1,%2,%3};\n" \
        : "+f"((acc)[0]), "+f"((acc)[1]), "+f"((acc)[2]), "+f"((acc)[3]) \
        : "r"(a0), "r"(a1), "r"(a2), "r"(a3), "r"(b0), "r"(b1))

#define LDSM_X4(r0,r1,r2,r3,addr) \
    asm volatile("ldmatrix.sync.aligned.m8n8.x4.shared.b16 {%0,%1,%2,%3}, [%4];" \
        : "=r"(r0), "=r"(r1), "=r"(r2), "=r"(r3) : "r"(addr))

// ---------------- CSR build --------------------------------------------------
__global__ void k_zero(int n){
    int i = blockIdx.x*blockDim.x + threadIdx.x;
    if (i < n) g_deg[i] = 0;
}

__global__ void k_hist(const int* __restrict__ dst, int E){
    int e = blockIdx.x*blockDim.x + threadIdx.x;
    if (e < E) atomicAdd(&g_deg[dst[e]], 1);
}

__global__ void k_scan(int n){
    __shared__ int ss[1024];
    int t = threadIdx.x;
    int chunk = (n + 1023) >> 10;
    int lo = t*chunk;
    int hi = min(lo + chunk, n);
    int s = 0;
    for (int i = lo; i < hi; i++) s += g_deg[i];
    ss[t] = s;
    __syncthreads();
    for (int off = 1; off < 1024; off <<= 1){
        int v = (t >= off) ? ss[t-off] : 0;
        __syncthreads();
        ss[t] += v;
        __syncthreads();
    }
    int run = (t == 0) ? 0 : ss[t-1];
    for (int i = lo; i < hi; i++){
        g_rowptr[i] = run;
        g_cursor[i] = run;
        run += g_deg[i];
    }
    if (t == 1023) g_rowptr[n] = ss[1023];
}

__global__ void k_scatter(const int* __restrict__ src, const int* __restrict__ dst, int E){
    int e = blockIdx.x*blockDim.x + threadIdx.x;
    if (e < E){
        int d = dst[e];
        int p = atomicAdd(&g_cursor[d], 1);
        g_srcs[p] = src[e];
    }
}

// ---------------- merged prep: blocked x + blocked Wuv + lin-transpose -------
__global__ void k_prep(const float* __restrict__ x, const float* __restrict__ W_pre,
                       const float* __restrict__ W_lin, int N){
    int stride = gridDim.x*blockDim.x;
    int i0 = blockIdx.x*blockDim.x + threadIdx.x;
    for (int i = i0; i < N*FDIM; i += stride){
        int node = i >> 7, col = i & 127;
        g_xb[((size_t)(node >> 7)*4 + (col >> 5))*BLKH + (node & 127)*PITCH + (col & 31)]
            = __float2half_rn(x[i]);
    }
    for (int i = i0; i < 256*128; i += stride){
        int j = i >> 7, k = i & 127;
        float val = W_pre[(size_t)(j & 127)*256 + ((j >> 7) ? (128 + k) : k)];
        g_wuvb[((size_t)(j >> 7)*4 + (k >> 5))*BLKH + (j & 127)*PITCH + (k & 31)]
            = __float2half_rn(val);
    }
    for (int i = i0; i < FDIM*FDIM; i += stride){
        int f = i >> 7, c = i & 127;
        g_Wt_lin[c*FDIM + f] = W_lin[i];
    }
}

// blocked W_comb: g_wcb[chunk=c>>5][f][c&31]; block KPOST computes bias
__global__ void k_combine(const float* __restrict__ W_post,
                          const float* __restrict__ b_post,
                          const float* __restrict__ b_lin){
    int f = threadIdx.x;
    if (blockIdx.x == KPOST){
        float s = b_lin[f];
        #pragma unroll 8
        for (int k = 0; k < FDIM; k++)
            s = fmaf(g_Wt_lin[k*FDIM + f], b_post[k], s);
        g_b_comb[f] = s;
        return;
    }
    int c = blockIdx.x;
    __shared__ float col[FDIM];
    col[f] = W_post[(size_t)f*KPOST + c];
    __syncthreads();
    float s = 0.f;
    #pragma unroll 8
    for (int k = 0; k < FDIM; k++)
        s = fmaf(g_Wt_lin[k*FDIM + f], col[k], s);
    g_wcb[(size_t)(c >> 5)*BLKH + f*PITCH + (c & 31)] = __float2half_rn(s);
}

// ---------------- u/v FP16 GEMM: bulk-copy pipelined (K=128) -----------------
// gridDim.y: 0 -> u (fp32 + bias), 1 -> v (fp16, no bias)
__global__ void __launch_bounds__(256, 2)
k_uv_f16(int M, const float* __restrict__ b_pre)
{
    __shared__ __align__(16) __half st[2][2*BLKH];   // [stage][A | W]
    __shared__ __align__(16) uint64_t barsto[2];

    int tid  = threadIdx.x;
    int bi   = blockIdx.x;
    int m0   = bi * 128;
    int half_ = blockIdx.y;
    int wid  = tid >> 5, lane = tid & 31;
    int wm   = (wid >> 1) * 32;
    int wn   = (wid & 1) * 64;
    int grp  = lane >> 2, qid = lane & 3;

    int arow  = (lane & 7) + ((lane >> 3) & 1) * 8;
    int aksel = (lane >> 4) * 8;
    int brow  = (lane & 7) + ((lane >> 4) ? 8 : 0);
    int bksel = ((lane >> 3) & 1) * 8;

    uint32_t bars[2] = { s2u(&barsto[0]), s2u(&barsto[1]) };
    if (tid == 0){ mbar_init(bars[0], 1); mbar_init(bars[1], 1); }
    __syncthreads();

    float acc[2][8][4];
    #pragma unroll
    for (int mt = 0; mt < 2; mt++)
        #pragma unroll
        for (int nt = 0; nt < 8; nt++)
            #pragma unroll
            for (int q = 0; q < 4; q++) acc[mt][nt][q] = 0.f;

    auto issue = [&](int t){
        int buf = t & 1;
        mbar_expect_tx(bars[buf], 2*BLKB);
        bulk_g2s(s2u(&st[buf][0]),    g_xb + ((size_t)bi*4 + t)*BLKH,         BLKB, bars[buf]);
        bulk_g2s(s2u(&st[buf][BLKH]), g_wuvb + ((size_t)half_*4 + t)*BLKH,    BLKB, bars[buf]);
    };

    const int T = 4;
    if (tid == 0){ issue(0); issue(1); }

    for (int t = 0; t < T; t++){
        int cur = t & 1;
        mbar_wait(bars[cur], (t >> 1) & 1);
        const __half* A = &st[cur][0];
        const __half* W = &st[cur][BLKH];
        #pragma unroll
        for (int ks = 0; ks < 2; ks++){
            int kk = ks*16;
            uint32_t a[2][4], b[8][2];
            #pragma unroll
            for (int mt = 0; mt < 2; mt++){
                uint32_t addr = s2u(&A[(wm + mt*16 + arow)*PITCH + kk + aksel]);
                LDSM_X4(a[mt][0], a[mt][1], a[mt][2], a[mt][3], addr);
            }
            #pragma unroll
            for (int p = 0; p < 4; p++){
                uint32_t addr = s2u(&W[(wn + p*16 + brow)*PITCH + kk + bksel]);
                LDSM_X4(b[2*p][0], b[2*p][1], b[2*p+1][0], b[2*p+1][1], addr);
            }
            #pragma unroll
            for (int mt = 0; mt < 2; mt++)
                #pragma unroll
                for (int nt = 0; nt < 8; nt++)
                    MMA_F16(acc[mt][nt], a[mt][0],a[mt][1],a[mt][2],a[mt][3],
                            b[nt][0], b[nt][1]);
        }
        __syncthreads();
        if (t + 2 < T && tid == 0) issue(t + 2);
    }

    #pragma unroll
    for (int mt = 0; mt < 2; mt++){
        int row0 = m0 + wm + mt*16 + grp;
        #pragma unroll
        for (int nt = 0; nt < 8; nt++){
            int col = wn + nt*8 + 2*qid;
            if (half_){
                if (row0 < M)
                    *(__half2*)(g_vh + (size_t)row0*128 + col) =
                        __floats2half2_rn(acc[mt][nt][0], acc[mt][nt][1]);
                if (row0 + 8 < M)
                    *(__half2*)(g_vh + (size_t)(row0+8)*128 + col) =
                        __floats2half2_rn(acc[mt][nt][2], acc[mt][nt][3]);
            } else {
                float b0 = b_pre[col], b1 = b_pre[col+1];
                if (row0 < M)
                    *(float2*)(g_u + (size_t)row0*128 + col) =
                        make_float2(acc[mt][nt][0] + b0, acc[mt][nt][1] + b1);
                if (row0 + 8 < M)
                    *(float2*)(g_u + (size_t)(row0+8)*128 + col) =
                        make_float2(acc[mt][nt][2] + b0, acc[mt][nt][3] + b1);
            }
        }
    }
}

// ---------------- per-node aggregation (factored u, fp16 v gathers) ----------
// writes agg in blocked layout
__global__ void k_agg(int n){
    int node = blockIdx.x*2 + (threadIdx.x >> 6);
    int t = threadIdx.x & 63;
    if (node >= n) return;
    int s0 = g_rowptr[node], s1 = g_rowptr[node+1];
    const __half2* vh = (const __half2*)g_vh;

    __half2 hmx = __half2half2(__ushort_as_half((unsigned short)0xFC00));  // -inf
    __half2 hmn = __half2half2(__ushort_as_half((unsigned short)0x7C00));  // +inf
    float smx = 0.f, smy = 0.f, sqx = 0.f, sqy = 0.f;

    int e = s0;
    for (; e + 3 < s1; e += 4){
        int i0 = g_srcs[e], i1 = g_srcs[e+1], i2 = g_srcs[e+2], i3 = g_srcs[e+3];
        __half2 v0 = vh[(size_t)i0*64 + t];
        __half2 v1 = vh[(size_t)i1*64 + t];
        __half2 v2 = vh[(size_t)i2*64 + t];
        __half2 v3 = vh[(size_t)i3*64 + t];
        hmx = __hmax2(hmx, __hmax2(__hmax2(v0, v1), __hmax2(v2, v3)));
        hmn = __hmin2(hmn, __hmin2(__hmin2(v0, v1), __hmin2(v2, v3)));
        float2 f0 = __half22float2(v0), f1 = __half22float2(v1);
        float2 f2 = __half22float2(v2), f3 = __half22float2(v3);
        smx += f0.x + f1.x + f2.x + f3.x;
        smy += f0.y + f1.y + f2.y + f3.y;
        sqx = fmaf(f0.x, f0.x, sqx); sqx = fmaf(f1.x, f1.x, sqx);
        sqx = fmaf(f2.x, f2.x, sqx); sqx = fmaf(f3.x, f3.x, sqx);
        sqy = fmaf(f0.y, f0.y, sqy); sqy = fmaf(f1.y, f1.y, sqy);
        sqy = fmaf(f2.y, f2.y, sqy); sqy = fmaf(f3.y, f3.y, sqy);
    }
    for (; e < s1; e++){
        int s = g_srcs[e];
        __half2 v = vh[(size_t)s*64 + t];
        hmx = __hmax2(hmx, v);
        hmn = __hmin2(hmn, v);
        float2 f = __half22float2(v);
        smx += f.x; smy += f.y;
        sqx = fmaf(f.x, f.x, sqx);
        sqy = fmaf(f.y, f.y, sqy);
    }

    int deg = s1 - s0;
    float dc = fmaxf((float)deg, 1.f);
    float inv = 1.f / dc;
    float2 uf = *(const float2*)(g_u + (size_t)node*128 + 2*t);

    float vmx_x = __half2float(__low2half(hmx)),  vmx_y = __half2float(__high2half(hmx));
    float vmn_x = __half2float(__low2half(hmn)),  vmn_y = __half2float(__high2half(hmn));
    float vme_x = smx*inv, vme_y = smy*inv;

    float outv[4][2];
    outv[0][0] = deg ? (uf.x + vmx_x) : 0.f;
    outv[0][1] = deg ? (uf.y + vmx_y) : 0.f;
    outv[1][0] = deg ? (uf.x + vmn_x) : 0.f;
    outv[1][1] = deg ? (uf.y + vmn_y) : 0.f;
    outv[2][0] = deg ? (uf.x + vme_x) : 0.f;
    outv[2][1] = deg ? (uf.y + vme_y) : 0.f;
    outv[3][0] = sqrtf(fmaxf(sqx*inv - vme_x*vme_x, 0.f) + 1e-5f);
    outv[3][1] = sqrtf(fmaxf(sqy*inv - vme_y*vme_y, 0.f) + 1e-5f);

    // blocked write: agg col c = a*128 + 2t -> chunk = a*4 + (t>>4), off = (2t)&31
    size_t base = (size_t)(node >> 7)*16*BLKH + (node & 127)*PITCH;
    int off = (2*t) & 31;
    int csub = t >> 4;
    #pragma unroll
    for (int a = 0; a < 4; a++){
        __half2 h = __floats2half2_rn(outv[a][0], outv[a][1]);
        *(__half2*)(g_aggb + base + (size_t)(a*4 + csub)*BLKH + off) = h;
    }

    if (t == 0){
        float ld = logf(dc + 1.f);   // DELTA = 1.0
        g_amp[node] = ld;
        g_att[node] = 1.f / ld;
    }
}

// ---------------- factored FP16 post GEMM (bulk-copy pipelined) --------------
// out = x@W0 + agg@W1 + amp.*(agg@W2) + att.*(agg@W3) + b_comb
#define P_STAGE (4*BLKH)                  /* A + 3 W slots (halves) */
#define POST_SMEM_BYTES (2*P_STAGE*2)     /* 81920 B */

__global__ void __launch_bounds__(256, 1)
k_post3(int M, float* __restrict__ C)
{
    extern __shared__ __align__(16) __half smh[];
    __shared__ __align__(16) uint64_t barsto[2];

    int tid  = threadIdx.x;
    int bi   = blockIdx.x;
    int m0   = bi * 128;
    int wid  = tid >> 5, lane = tid & 31;
    int wm   = (wid >> 1) * 32;
    int wn   = (wid & 1) * 64;
    int grp  = lane >> 2, qid = lane & 3;

    int arow  = (lane & 7) + ((lane >> 3) & 1) * 8;
    int aksel = (lane >> 4) * 8;
    int brow  = (lane & 7) + ((lane >> 4) ? 8 : 0);
    int bksel = ((lane >> 3) & 1) * 8;

    uint32_t bars[2] = { s2u(&barsto[0]), s2u(&barsto[1]) };
    if (tid == 0){ mbar_init(bars[0], 1); mbar_init(bars[1], 1); }
    __syncthreads();

    float accC[2][8][4], accA[2][8][4], accT[2][8][4];
    #pragma unroll
    for (int mt = 0; mt < 2; mt++)
        #pragma unroll
        for (int nt = 0; nt < 8; nt++)
            #pragma unroll
            for (int q = 0; q < 4; q++){
                accC[mt][nt][q] = 0.f; accA[mt][nt][q] = 0.f; accT[mt][nt][q] = 0.f;
            }

    auto issue = [&](int t){
        int buf = t & 1;
        uint32_t sA  = s2u(&smh[buf*P_STAGE]);
        if (t < 4){
            mbar_expect_tx(bars[buf], 2*BLKB);
            bulk_g2s(sA,        g_xb + ((size_t)bi*4 + t)*BLKH, BLKB, bars[buf]);
            bulk_g2s(sA + BLKB, g_wcb + (size_t)t*BLKH,         BLKB, bars[buf]);
        } else {
            int ka = t - 4;
            mbar_expect_tx(bars[buf], 4*BLKB);
            bulk_g2s(sA,          g_aggb + ((size_t)bi*16 + ka)*BLKH, BLKB, bars[buf]);
            bulk_g2s(sA + 1*BLKB, g_wcb + (size_t)(4  + ka)*BLKH,     BLKB, bars[buf]);
            bulk_g2s(sA + 2*BLKB, g_wcb + (size_t)(20 + ka)*BLKH,     BLKB, bars[buf]);
            bulk_g2s(sA + 3*BLKB, g_wcb + (size_t)(36 + ka)*BLKH,     BLKB, bars[buf]);
        }
    };

    const int T = 20;
    if (tid == 0){ issue(0); issue(1); }

    for (int t = 0; t < T; t++){
        int cur = t & 1;
        mbar_wait(bars[cur], (t >> 1) & 1);
        const __half* S = &smh[cur*P_STAGE];
        int nsets = (t < 4) ? 1 : 3;
        #pragma unroll
        for (int ks = 0; ks < 2; ks++){
            int kk = ks*16;
            uint32_t a[2][4];
            #pragma unroll
            for (int mt = 0; mt < 2; mt++){
                uint32_t addr = s2u(&S[(wm + mt*16 + arow)*PITCH + kk + aksel]);
                LDSM_X4(a[mt][0], a[mt][1], a[mt][2], a[mt][3], addr);
            }
            #pragma unroll
            for (int s = 0; s < 3; s++){
                if (s >= nsets) break;
                const __half* W = S + (1 + s)*BLKH;
                uint32_t b[8][2];
                #pragma unroll
                for (int p = 0; p < 4; p++){
                    uint32_t addr = s2u(&W[(wn + p*16 + brow)*PITCH + kk + bksel]);
                    LDSM_X4(b[2*p][0], b[2*p][1], b[2*p+1][0], b[2*p+1][1], addr);
                }
                float (*acc)[8][4] = (s == 0) ? accC : (s == 1) ? accA : accT;
                #pragma unroll
                for (int mt = 0; mt < 2; mt++)
                    #pragma unroll
                    for (int nt = 0; nt < 8; nt++)
                        MMA_F16(acc[mt][nt], a[mt][0],a[mt][1],a[mt][2],a[mt][3],
                                b[nt][0], b[nt][1]);
            }
        }
        __syncthreads();
        if (t + 2 < T && tid == 0) issue(t + 2);
    }

    #pragma unroll
    for (int mt = 0; mt < 2; mt++){
        int row0 = m0 + wm + mt*16 + grp;
        int row1 = row0 + 8;
        float amp0 = 0.f, att0 = 0.f, amp1 = 0.f, att1 = 0.f;
        if (row0 < M){ amp0 = g_amp[row0]; att0 = g_att[row0]; }
        if (row1 < M){ amp1 = g_amp[row1]; att1 = g_att[row1]; }
        #pragma unroll
        for (int nt = 0; nt < 8; nt++){
            int col = wn + nt*8 + 2*qid;
            float b0 = g_b_comb[col], b1 = g_b_comb[col+1];
            if (row0 < M){
                float2 v;
                v.x = accC[mt][nt][0] + amp0*accA[mt][nt][0] + att0*accT[mt][nt][0] + b0;
                v.y = accC[mt][nt][1] + amp0*accA[mt][nt][1] + att0*accT[mt][nt][1] + b1;
                *(float2*)(C + (size_t)row0*128 + col) = v;
            }
            if (row1 < M){
                float2 v;
                v.x = accC[mt][nt][2] + amp1*accA[mt][nt][2] + att1*accT[mt][nt][2] + b0;
                v.y = accC[mt][nt][3] + amp1*accA[mt][nt][3] + att1*accT[mt][nt][3] + b1;
                *(float2*)(C + (size_t)row1*128 + col) = v;
            }
        }
    }
}

// ---------------- launch -----------------------------------------------------
extern "C" void kernel_launch(void* const* d_in, const int* in_sizes, int n_in,
                              void* d_out, int out_size)
{
    const float* x      = (const float*)d_in[0];
    const int*   ei     = (const int*)  d_in[1];
    const float* W_pre  = (const float*)d_in[2];
    const float* b_pre  = (const float*)d_in[3];
    const float* W_post = (const float*)d_in[4];
    const float* b_post = (const float*)d_in[5];
    const float* W_lin  = (const float*)d_in[6];
    const float* b_lin  = (const float*)d_in[7];
    float* out = (float*)d_out;

    int N = in_sizes[0] / FDIM;
    int E = in_sizes[1] / 2;
    const int* src = ei;        // edge_index[0] = x_j (source)
    const int* dst = ei + E;    // edge_index[1] = x_i (destination)

    cudaFuncSetAttribute(k_post3,
                         cudaFuncAttributeMaxDynamicSharedMemorySize, POST_SMEM_BYTES);

    // CSR build
    k_zero   <<<(N+255)/256, 256>>>(N);
    k_hist   <<<(E+255)/256, 256>>>(dst, E);
    k_scan   <<<1, 1024>>>(N);
    k_scatter<<<(E+255)/256, 256>>>(src, dst, E);

    // merged prep (blocked layouts) + combined weights
    k_prep<<<(N*FDIM+255)/256, 256>>>(x, W_pre, W_lin, N);
    k_combine<<<KPOST+1, FDIM>>>(W_post, b_post, b_lin);

    // u/v fp16 GEMM (bulk pipelined)
    int gm = (N + 127) / 128;
    dim3 guv(gm, 2);
    k_uv_f16<<<guv, 256>>>(N, b_pre);

    // factored aggregation (fp16 gathers, blocked agg out)
    k_agg<<<(N+1)/2, 128>>>(N);

    // factored fp16 post GEMM (bulk pipelined)
    k_post3<<<gm, 256, POST_SMEM_BYTES>>>(N, out);
}